// round 1
// baseline (speedup 1.0000x reference)
#include <cuda_runtime.h>
#include <math.h>

#define Bn 4
#define Qn 8192
#define Dm 256
#define Lv 2
#define Pp 8
#define H0 128
#define W0 128
#define H1 64
#define W1 64
#define EPSV 1e-5f

// Scratch (device globals — no allocations allowed)
__device__ float g_map0[Bn * H0 * W0 * Dm];   // (B, H*W, D) HWC
__device__ float g_map1[Bn * H1 * W1 * Dm];   // (B, H*W, D) HWC
__device__ float g_pre [Bn * Qn * Dm];        // pre-Wout accumulator

// ---------------------------------------------------------------------------
// Kernel 1: (B, D, HW) -> (B, HW, D) tiled transpose
// ---------------------------------------------------------------------------
__global__ __launch_bounds__(256) void transpose_kernel(
    const float* __restrict__ in, int HW, int level)
{
    __shared__ float tile[32][33];
    float* out = level ? g_map1 : g_map0;

    int hw0 = blockIdx.x * 32;
    int d0  = blockIdx.y * 32;
    int b   = blockIdx.z;
    int tx = threadIdx.x;      // 0..31
    int ty = threadIdx.y;      // 0..7

    const float* inb = in + (size_t)b * Dm * HW;
    float* outb = out + (size_t)b * HW * Dm;

#pragma unroll
    for (int i = 0; i < 4; i++) {
        int d = d0 + ty + 8 * i;
        tile[ty + 8 * i][tx] = inb[(size_t)d * HW + hw0 + tx];
    }
    __syncthreads();
#pragma unroll
    for (int i = 0; i < 4; i++) {
        int hw = hw0 + ty + 8 * i;
        outb[(size_t)hw * Dm + d0 + tx] = tile[tx][ty + 8 * i];
    }
}

// ---------------------------------------------------------------------------
// Kernel 2: per-query block. Projections + softmax + coords + bilinear gather.
// grid = (Qn, Bn), block = 256 (thread = output channel)
// ---------------------------------------------------------------------------
__global__ __launch_bounds__(256) void dca_main_kernel(
    const float* __restrict__ q,
    const float* __restrict__ base_ref,
    const float* __restrict__ Wrd,  const float* __restrict__ brd,
    const float* __restrict__ Woff, const float* __restrict__ boff,
    const float* __restrict__ Wattn,const float* __restrict__ battn)
{
    __shared__ float qs[256];
    __shared__ float dots[52];
    __shared__ float s_wx[16], s_wy[16], s_e[16];
    __shared__ int   s_o00[16], s_o01[16], s_o10[16], s_o11[16];
    __shared__ float s_einv;

    const int qi = blockIdx.x;
    const int b  = blockIdx.y;
    const int tid  = threadIdx.x;
    const int lane = tid & 31;
    const int wid  = tid >> 5;

    qs[tid] = q[((size_t)(b * Qn + qi)) * Dm + tid];
    __syncthreads();

    // 52 dot products: dots[0..3]=ref_delta, [4..35]=offsets, [36..51]=attn logits
    for (int j = wid; j < 52; j += 8) {
        const float* W; int stride, col; const float* bias;
        if (j < 4)       { W = Wrd;   stride = 4;  col = j;      bias = brd   + col; }
        else if (j < 36) { W = Woff;  stride = 32; col = j - 4;  bias = boff  + col; }
        else             { W = Wattn; stride = 16; col = j - 36; bias = battn + col; }
        float s = 0.f;
#pragma unroll
        for (int k = lane; k < 256; k += 32)
            s += qs[k] * __ldg(&W[k * stride + col]);
#pragma unroll
        for (int o = 16; o; o >>= 1)
            s += __shfl_xor_sync(0xffffffffu, s, o);
        if (lane == 0) dots[j] = s + __ldg(bias);
    }
    __syncthreads();

    // Warp 0: softmax over 16 logits + sample-point geometry
    if (wid == 0) {
        int p = lane;
        float logit = (p < 16) ? dots[36 + p] : -1e30f;
        float m = logit;
#pragma unroll
        for (int o = 16; o; o >>= 1)
            m = fmaxf(m, __shfl_xor_sync(0xffffffffu, m, o));
        float e = (p < 16) ? expf(logit - m) : 0.f;
        float esum = e;
#pragma unroll
        for (int o = 16; o; o >>= 1)
            esum += __shfl_xor_sync(0xffffffffu, esum, o);
        if (p == 0) s_einv = 1.f / esum;

        if (p < 16) {
            s_e[p] = e;
            const int l  = p >> 3;
            const int pp = p & 7;
            const int Wl = l ? W1 : W0;
            const int Hl = l ? H1 : H0;

            float bx = base_ref[(b * Lv + l) * 2 + 0];
            float by = base_ref[(b * Lv + l) * 2 + 1];
            bx = fminf(fmaxf(bx, EPSV), 1.f - EPSV);
            by = fminf(fmaxf(by, EPSV), 1.f - EPSV);
            float lbx = logf(bx / (1.f - bx));
            float lby = logf(by / (1.f - by));
            float rx = 1.f / (1.f + expf(-(lbx + dots[l * 2 + 0])));
            float ry = 1.f / (1.f + expf(-(lby + dots[l * 2 + 1])));

            float ox = dots[4 + l * 16 + pp * 2 + 0];
            float oy = dots[4 + l * 16 + pp * 2 + 1];
            float lx = rx + ox / (float)Wl;
            float ly = ry + oy / (float)Hl;
            if (l == 1) ly = ly - floorf(ly);   // jnp.remainder(ly, 1.0)

            // grid_sample unnormalize (align_corners=False): x = loc*W - 0.5
            float x = lx * (float)Wl - 0.5f;
            float y = ly * (float)Hl - 0.5f;
            x = fminf(fmaxf(x, 0.f), (float)(Wl - 1));
            y = fminf(fmaxf(y, 0.f), (float)(Hl - 1));
            float x0f = floorf(x), y0f = floorf(y);
            s_wx[p] = x - x0f;
            s_wy[p] = y - y0f;
            int x0 = (int)x0f, y0 = (int)y0f;
            int x1 = min(x0 + 1, Wl - 1);
            int y1 = min(y0 + 1, Hl - 1);
            int base = b * Hl * Wl * Dm;
            s_o00[p] = base + (y0 * Wl + x0) * Dm;
            s_o01[p] = base + (y0 * Wl + x1) * Dm;
            s_o10[p] = base + (y1 * Wl + x0) * Dm;
            s_o11[p] = base + (y1 * Wl + x1) * Dm;
        }
    }
    __syncthreads();

    // Gather + weighted accumulate. thread = channel, loads coalesced (HWC).
    const int c = tid;
    float acc = 0.f;
#pragma unroll
    for (int p = 0; p < 16; p++) {
        const float* mp = (p < 8) ? g_map0 : g_map1;
        float v00 = __ldg(&mp[s_o00[p] + c]);
        float v01 = __ldg(&mp[s_o01[p] + c]);
        float v10 = __ldg(&mp[s_o10[p] + c]);
        float v11 = __ldg(&mp[s_o11[p] + c]);
        float wx = s_wx[p], wy = s_wy[p];
        float top = v00 + wx * (v01 - v00);
        float bot = v10 + wx * (v11 - v10);
        acc += s_e[p] * (top + wy * (bot - top));
    }
    g_pre[((size_t)(b * Qn + qi)) * Dm + c] = acc * s_einv;
}

// ---------------------------------------------------------------------------
// Kernel 3: C = g_pre(M,256) @ Wout(256,256) + bout.  BM=BN=64, BK=32, 4x4/thr
// ---------------------------------------------------------------------------
#define BM 64
#define BN 64
#define BK 32

__global__ __launch_bounds__(256) void gemm_kernel(
    const float* __restrict__ Wt, const float* __restrict__ bias,
    float* __restrict__ C)
{
    __shared__ float As[BK][BM];   // A stored k-major (transposed)
    __shared__ float Bs[BK][BN];

    const int tid = threadIdx.x;
    const int m0 = blockIdx.y * BM;
    const int n0 = blockIdx.x * BN;
    const int tx = tid & 15;       // 0..15
    const int ty = tid >> 4;       // 0..15

    float acc[4][4] = {};

    for (int k0 = 0; k0 < 256; k0 += BK) {
        // A tile: 64x32 floats = 512 float4, 2 per thread
#pragma unroll
        for (int i = 0; i < 2; i++) {
            int idx = tid + i * 256;
            int r  = idx >> 3;     // row 0..63
            int c4 = idx & 7;      // float4 col 0..7
            float4 v = *(const float4*)&g_pre[(size_t)(m0 + r) * 256 + k0 + c4 * 4];
            As[c4 * 4 + 0][r] = v.x;
            As[c4 * 4 + 1][r] = v.y;
            As[c4 * 4 + 2][r] = v.z;
            As[c4 * 4 + 3][r] = v.w;
        }
        // B tile: 32x64 floats = 512 float4, 2 per thread
#pragma unroll
        for (int i = 0; i < 2; i++) {
            int idx = tid + i * 256;
            int r  = idx >> 4;     // row 0..31
            int c4 = idx & 15;     // float4 col 0..15
            *(float4*)&Bs[r][c4 * 4] =
                *(const float4*)&Wt[(size_t)(k0 + r) * 256 + n0 + c4 * 4];
        }
        __syncthreads();

#pragma unroll
        for (int kk = 0; kk < BK; kk++) {
            float4 a  = *(float4*)&As[kk][ty * 4];
            float4 bb = *(float4*)&Bs[kk][tx * 4];
            float av[4] = {a.x, a.y, a.z, a.w};
            float bv[4] = {bb.x, bb.y, bb.z, bb.w};
#pragma unroll
            for (int i = 0; i < 4; i++)
#pragma unroll
                for (int j = 0; j < 4; j++)
                    acc[i][j] += av[i] * bv[j];
        }
        __syncthreads();
    }

    float4 bb = *(const float4*)&bias[n0 + tx * 4];
    float bv[4] = {bb.x, bb.y, bb.z, bb.w};
#pragma unroll
    for (int i = 0; i < 4; i++) {
        int m = m0 + ty * 4 + i;
        float4 o;
        o.x = acc[i][0] + bv[0];
        o.y = acc[i][1] + bv[1];
        o.z = acc[i][2] + bv[2];
        o.w = acc[i][3] + bv[3];
        *(float4*)&C[(size_t)m * 256 + n0 + tx * 4] = o;
    }
}

// ---------------------------------------------------------------------------
extern "C" void kernel_launch(void* const* d_in, const int* in_sizes, int n_in,
                              void* d_out, int out_size)
{
    const float* q        = (const float*)d_in[0];
    const float* map0     = (const float*)d_in[1];
    const float* map1     = (const float*)d_in[2];
    const float* base_ref = (const float*)d_in[3];
    const float* Wrd      = (const float*)d_in[4];
    const float* brd      = (const float*)d_in[5];
    const float* Woff     = (const float*)d_in[6];
    const float* boff     = (const float*)d_in[7];
    const float* Wattn    = (const float*)d_in[8];
    const float* battn    = (const float*)d_in[9];
    const float* Wout     = (const float*)d_in[10];
    const float* bout     = (const float*)d_in[11];
    float* out = (float*)d_out;

    // 1) maps -> HWC
    transpose_kernel<<<dim3((H0 * W0) / 32, Dm / 32, Bn), dim3(32, 8)>>>(map0, H0 * W0, 0);
    transpose_kernel<<<dim3((H1 * W1) / 32, Dm / 32, Bn), dim3(32, 8)>>>(map1, H1 * W1, 1);

    // 2) projections + sampling -> g_pre
    dca_main_kernel<<<dim3(Qn, Bn), 256>>>(q, base_ref, Wrd, brd, Woff, boff, Wattn, battn);

    // 3) out = g_pre @ Wout + bout
    gemm_kernel<<<dim3(256 / BN, (Bn * Qn) / BM), 256>>>(Wout, bout, out);
}

// round 2
// speedup vs baseline: 3.2440x; 3.2440x over previous
#include <cuda_runtime.h>
#include <math.h>

#define Bn 4
#define Qn 8192
#define Dm 256
#define Lv 2
#define Pp 8
#define H0 128
#define W0 128
#define H1 64
#define W1 64
#define EPSV 1e-5f

// Scratch (device globals — no allocations allowed)
__device__ float g_map0[Bn * H0 * W0 * Dm];   // (B, H*W, D) HWC
__device__ float g_map1[Bn * H1 * W1 * Dm];   // (B, H*W, D) HWC
__device__ float g_pre [Bn * Qn * Dm];        // pre-Wout accumulator
__device__ float g_Wcat[52 * 256];            // packed transposed weights, row j = output j
__device__ float g_bcat[52];                  // packed biases

// ---------------------------------------------------------------------------
// Kernel 0: pack weights transposed. grid=52 blocks, 256 threads.
// j: 0..3 = Wrd cols, 4..35 = Woff cols, 36..51 = Wattn cols
// ---------------------------------------------------------------------------
__global__ __launch_bounds__(256) void pack_weights_kernel(
    const float* __restrict__ Wrd,  const float* __restrict__ brd,
    const float* __restrict__ Woff, const float* __restrict__ boff,
    const float* __restrict__ Wattn,const float* __restrict__ battn)
{
    int j = blockIdx.x;
    int k = threadIdx.x;
    const float* W; int stride, col; const float* bias;
    if (j < 4)       { W = Wrd;   stride = 4;  col = j;      bias = brd   + col; }
    else if (j < 36) { W = Woff;  stride = 32; col = j - 4;  bias = boff  + col; }
    else             { W = Wattn; stride = 16; col = j - 36; bias = battn + col; }
    g_Wcat[j * 256 + k] = W[k * stride + col];
    if (k == 0) g_bcat[j] = *bias;
}

// ---------------------------------------------------------------------------
// Kernel 1: (B, D, HW) -> (B, HW, D) tiled transpose
// ---------------------------------------------------------------------------
__global__ __launch_bounds__(256) void transpose_kernel(
    const float* __restrict__ in, int HW, int level)
{
    __shared__ float tile[32][33];
    float* out = level ? g_map1 : g_map0;

    int hw0 = blockIdx.x * 32;
    int d0  = blockIdx.y * 32;
    int b   = blockIdx.z;
    int tx = threadIdx.x;      // 0..31
    int ty = threadIdx.y;      // 0..7

    const float* inb = in + (size_t)b * Dm * HW;
    float* outb = out + (size_t)b * HW * Dm;

#pragma unroll
    for (int i = 0; i < 4; i++) {
        int d = d0 + ty + 8 * i;
        tile[ty + 8 * i][tx] = inb[(size_t)d * HW + hw0 + tx];
    }
    __syncthreads();
#pragma unroll
    for (int i = 0; i < 4; i++) {
        int hw = hw0 + ty + 8 * i;
        outb[(size_t)hw * Dm + d0 + tx] = tile[tx][ty + 8 * i];
    }
}

// ---------------------------------------------------------------------------
// Kernel 2: per-query block. Projections + softmax + coords + bilinear gather.
// grid = (Qn, Bn), block = 256 (thread = output channel)
// ---------------------------------------------------------------------------
__global__ __launch_bounds__(256) void dca_main_kernel(
    const float* __restrict__ q,
    const float* __restrict__ base_ref)
{
    __shared__ float qs[256];
    __shared__ float dots[52];
    __shared__ float s_wx[16], s_wy[16], s_e[16];
    __shared__ int   s_o00[16], s_o01[16], s_o10[16], s_o11[16];
    __shared__ float s_einv;

    const int qi = blockIdx.x;
    const int b  = blockIdx.y;
    const int tid  = threadIdx.x;
    const int lane = tid & 31;
    const int wid  = tid >> 5;

    qs[tid] = q[((size_t)(b * Qn + qi)) * Dm + tid];
    __syncthreads();

    // 52 dot products against packed, k-contiguous weights (coalesced loads).
    for (int j = wid; j < 52; j += 8) {
        const float* Wr = &g_Wcat[j * 256];
        float s = 0.f;
#pragma unroll
        for (int i = 0; i < 8; i++)
            s += qs[lane + 32 * i] * __ldg(&Wr[lane + 32 * i]);
#pragma unroll
        for (int o = 16; o; o >>= 1)
            s += __shfl_xor_sync(0xffffffffu, s, o);
        if (lane == 0) dots[j] = s + g_bcat[j];
    }
    __syncthreads();

    // Warp 0: softmax over 16 logits + sample-point geometry
    if (wid == 0) {
        int p = lane;
        float logit = (p < 16) ? dots[36 + p] : -1e30f;
        float m = logit;
#pragma unroll
        for (int o = 16; o; o >>= 1)
            m = fmaxf(m, __shfl_xor_sync(0xffffffffu, m, o));
        float e = (p < 16) ? expf(logit - m) : 0.f;
        float esum = e;
#pragma unroll
        for (int o = 16; o; o >>= 1)
            esum += __shfl_xor_sync(0xffffffffu, esum, o);
        if (p == 0) s_einv = 1.f / esum;

        if (p < 16) {
            s_e[p] = e;
            const int l  = p >> 3;
            const int pp = p & 7;
            const int Wl = l ? W1 : W0;
            const int Hl = l ? H1 : H0;

            float bx = base_ref[(b * Lv + l) * 2 + 0];
            float by = base_ref[(b * Lv + l) * 2 + 1];
            bx = fminf(fmaxf(bx, EPSV), 1.f - EPSV);
            by = fminf(fmaxf(by, EPSV), 1.f - EPSV);
            float lbx = logf(bx / (1.f - bx));
            float lby = logf(by / (1.f - by));
            float rx = 1.f / (1.f + expf(-(lbx + dots[l * 2 + 0])));
            float ry = 1.f / (1.f + expf(-(lby + dots[l * 2 + 1])));

            float ox = dots[4 + l * 16 + pp * 2 + 0];
            float oy = dots[4 + l * 16 + pp * 2 + 1];
            float lx = rx + ox / (float)Wl;
            float ly = ry + oy / (float)Hl;
            if (l == 1) ly = ly - floorf(ly);   // jnp.remainder(ly, 1.0)

            // grid_sample unnormalize (align_corners=False): x = loc*W - 0.5
            float x = lx * (float)Wl - 0.5f;
            float y = ly * (float)Hl - 0.5f;
            x = fminf(fmaxf(x, 0.f), (float)(Wl - 1));
            y = fminf(fmaxf(y, 0.f), (float)(Hl - 1));
            float x0f = floorf(x), y0f = floorf(y);
            s_wx[p] = x - x0f;
            s_wy[p] = y - y0f;
            int x0 = (int)x0f, y0 = (int)y0f;
            int x1 = min(x0 + 1, Wl - 1);
            int y1 = min(y0 + 1, Hl - 1);
            int base = b * Hl * Wl * Dm;
            s_o00[p] = base + (y0 * Wl + x0) * Dm;
            s_o01[p] = base + (y0 * Wl + x1) * Dm;
            s_o10[p] = base + (y1 * Wl + x0) * Dm;
            s_o11[p] = base + (y1 * Wl + x1) * Dm;
        }
    }
    __syncthreads();

    // Gather + weighted accumulate. thread = channel, loads coalesced (HWC).
    const int c = tid;
    float acc = 0.f;
#pragma unroll
    for (int p = 0; p < 16; p++) {
        const float* mp = (p < 8) ? g_map0 : g_map1;
        float v00 = __ldg(&mp[s_o00[p] + c]);
        float v01 = __ldg(&mp[s_o01[p] + c]);
        float v10 = __ldg(&mp[s_o10[p] + c]);
        float v11 = __ldg(&mp[s_o11[p] + c]);
        float wx = s_wx[p], wy = s_wy[p];
        float top = v00 + wx * (v01 - v00);
        float bot = v10 + wx * (v11 - v10);
        acc += s_e[p] * (top + wy * (bot - top));
    }
    g_pre[((size_t)(b * Qn + qi)) * Dm + c] = acc * s_einv;
}

// ---------------------------------------------------------------------------
// Kernel 3: C = g_pre(M,256) @ Wout(256,256) + bout.  BM=BN=64, BK=32, 4x4/thr
// ---------------------------------------------------------------------------
#define BM 64
#define BN 64
#define BK 32

__global__ __launch_bounds__(256) void gemm_kernel(
    const float* __restrict__ Wt, const float* __restrict__ bias,
    float* __restrict__ C)
{
    __shared__ float As[BK][BM];   // A stored k-major (transposed)
    __shared__ float Bs[BK][BN];

    const int tid = threadIdx.x;
    const int m0 = blockIdx.y * BM;
    const int n0 = blockIdx.x * BN;
    const int tx = tid & 15;       // 0..15
    const int ty = tid >> 4;       // 0..15

    float acc[4][4] = {};

    for (int k0 = 0; k0 < 256; k0 += BK) {
        // A tile: 64x32 floats = 512 float4, 2 per thread
#pragma unroll
        for (int i = 0; i < 2; i++) {
            int idx = tid + i * 256;
            int r  = idx >> 3;     // row 0..63
            int c4 = idx & 7;      // float4 col 0..7
            float4 v = *(const float4*)&g_pre[(size_t)(m0 + r) * 256 + k0 + c4 * 4];
            As[c4 * 4 + 0][r] = v.x;
            As[c4 * 4 + 1][r] = v.y;
            As[c4 * 4 + 2][r] = v.z;
            As[c4 * 4 + 3][r] = v.w;
        }
        // B tile: 32x64 floats = 512 float4, 2 per thread
#pragma unroll
        for (int i = 0; i < 2; i++) {
            int idx = tid + i * 256;
            int r  = idx >> 4;     // row 0..31
            int c4 = idx & 15;     // float4 col 0..15
            *(float4*)&Bs[r][c4 * 4] =
                *(const float4*)&Wt[(size_t)(k0 + r) * 256 + n0 + c4 * 4];
        }
        __syncthreads();

#pragma unroll
        for (int kk = 0; kk < BK; kk++) {
            float4 a  = *(float4*)&As[kk][ty * 4];
            float4 bb = *(float4*)&Bs[kk][tx * 4];
            float av[4] = {a.x, a.y, a.z, a.w};
            float bv[4] = {bb.x, bb.y, bb.z, bb.w};
#pragma unroll
            for (int i = 0; i < 4; i++)
#pragma unroll
                for (int j = 0; j < 4; j++)
                    acc[i][j] += av[i] * bv[j];
        }
        __syncthreads();
    }

    float4 bb = *(const float4*)&bias[n0 + tx * 4];
    float bv[4] = {bb.x, bb.y, bb.z, bb.w};
#pragma unroll
    for (int i = 0; i < 4; i++) {
        int m = m0 + ty * 4 + i;
        float4 o;
        o.x = acc[i][0] + bv[0];
        o.y = acc[i][1] + bv[1];
        o.z = acc[i][2] + bv[2];
        o.w = acc[i][3] + bv[3];
        *(float4*)&C[(size_t)m * 256 + n0 + tx * 4] = o;
    }
}

// ---------------------------------------------------------------------------
extern "C" void kernel_launch(void* const* d_in, const int* in_sizes, int n_in,
                              void* d_out, int out_size)
{
    const float* q        = (const float*)d_in[0];
    const float* map0     = (const float*)d_in[1];
    const float* map1     = (const float*)d_in[2];
    const float* base_ref = (const float*)d_in[3];
    const float* Wrd      = (const float*)d_in[4];
    const float* brd      = (const float*)d_in[5];
    const float* Woff     = (const float*)d_in[6];
    const float* boff     = (const float*)d_in[7];
    const float* Wattn    = (const float*)d_in[8];
    const float* battn    = (const float*)d_in[9];
    const float* Wout     = (const float*)d_in[10];
    const float* bout     = (const float*)d_in[11];
    float* out = (float*)d_out;

    // 0) pack projection weights (one-time tiny cost per launch)
    pack_weights_kernel<<<52, 256>>>(Wrd, brd, Woff, boff, Wattn, battn);

    // 1) maps -> HWC
    transpose_kernel<<<dim3((H0 * W0) / 32, Dm / 32, Bn), dim3(32, 8)>>>(map0, H0 * W0, 0);
    transpose_kernel<<<dim3((H1 * W1) / 32, Dm / 32, Bn), dim3(32, 8)>>>(map1, H1 * W1, 1);

    // 2) projections + sampling -> g_pre
    dca_main_kernel<<<dim3(Qn, Bn), 256>>>(q, base_ref);

    // 3) out = g_pre @ Wout + bout
    gemm_kernel<<<dim3(256 / BN, (Bn * Qn) / BM), 256>>>(Wout, bout, out);
}

// round 3
// speedup vs baseline: 4.5136x; 1.3914x over previous
#include <cuda_runtime.h>
#include <math.h>

#define Bn 4
#define Qn 8192
#define Dm 256
#define Lv 2
#define Pp 8
#define H0 128
#define W0 128
#define H1 64
#define W1 64
#define EPSV 1e-5f
#define NQ (Bn * Qn)          // 32768 total queries

// Scratch (device globals — no allocations allowed)
__device__ float  g_map0[Bn * H0 * W0 * Dm];   // (B, H*W, D) HWC fp32
__device__ float  g_map1[Bn * H1 * W1 * Dm];
__device__ float  g_pre [NQ * Dm];             // pre-Wout accumulator
__device__ float  g_WcatP[64 * 256];           // packed transposed weights (52 used, zero pad)
__device__ float  g_bcatP[64];
__device__ float  g_dots[NQ * 64];             // projection outputs per query
__device__ int4   g_soff[NQ * 16];             // per (q,p): 4 corner element-offsets
__device__ float4 g_swt [NQ * 16];             // per (q,p): wx, wy, attn_w, 0

// ---------------------------------------------------------------------------
// Kernel 0: pack weights transposed into 64x256 (rows 52..63 zero).
// j: 0..3 = Wrd cols, 4..35 = Woff cols, 36..51 = Wattn cols
// ---------------------------------------------------------------------------
__global__ __launch_bounds__(256) void pack_weights_kernel(
    const float* __restrict__ Wrd,  const float* __restrict__ brd,
    const float* __restrict__ Woff, const float* __restrict__ boff,
    const float* __restrict__ Wattn,const float* __restrict__ battn)
{
    int j = blockIdx.x;
    int k = threadIdx.x;
    float v = 0.f, bv = 0.f;
    if (j < 4)       { v = Wrd  [k * 4  + j];      bv = brd  [j]; }
    else if (j < 36) { v = Woff [k * 32 + (j-4)];  bv = boff [j-4]; }
    else if (j < 52) { v = Wattn[k * 16 + (j-36)]; bv = battn[j-36]; }
    g_WcatP[j * 256 + k] = v;
    if (k == 0) g_bcatP[j] = bv;
}

// ---------------------------------------------------------------------------
// Kernel 1: (B, D, HW) -> (B, HW, D) tiled transpose
// ---------------------------------------------------------------------------
__global__ __launch_bounds__(256) void transpose_kernel(
    const float* __restrict__ in, int HW, int level)
{
    __shared__ float tile[32][33];
    float* out = level ? g_map1 : g_map0;

    int hw0 = blockIdx.x * 32;
    int d0  = blockIdx.y * 32;
    int b   = blockIdx.z;
    int tx = threadIdx.x;
    int ty = threadIdx.y;

    const float* inb = in + (size_t)b * Dm * HW;
    float* outb = out + (size_t)b * HW * Dm;

#pragma unroll
    for (int i = 0; i < 4; i++) {
        int d = d0 + ty + 8 * i;
        tile[ty + 8 * i][tx] = inb[(size_t)d * HW + hw0 + tx];
    }
    __syncthreads();
#pragma unroll
    for (int i = 0; i < 4; i++) {
        int hw = hw0 + ty + 8 * i;
        outb[(size_t)hw * Dm + d0 + tx] = tile[tx][ty + 8 * i];
    }
}

// ---------------------------------------------------------------------------
// Kernel 2: projection GEMM  g_dots[NQ][64] = q(NQ x 256) @ WcatP^T + bcatP
// BM=64, BN=64, BK=32, 4x4 microtile
// ---------------------------------------------------------------------------
__global__ __launch_bounds__(256) void proj_gemm_kernel(const float* __restrict__ q)
{
    __shared__ float As[32][64];
    __shared__ float Bs[32][64];

    const int tid = threadIdx.x;
    const int m0 = blockIdx.x * 64;
    const int tx = tid & 15;
    const int ty = tid >> 4;

    float acc[4][4] = {};

    for (int k0 = 0; k0 < 256; k0 += 32) {
        // A tile: 64 rows x 32 k (from q), store k-major
#pragma unroll
        for (int i = 0; i < 2; i++) {
            int idx = tid + i * 256;
            int r  = idx >> 3;
            int c4 = idx & 7;
            float4 v = *(const float4*)&q[(size_t)(m0 + r) * 256 + k0 + c4 * 4];
            As[c4 * 4 + 0][r] = v.x;
            As[c4 * 4 + 1][r] = v.y;
            As[c4 * 4 + 2][r] = v.z;
            As[c4 * 4 + 3][r] = v.w;
        }
        // B tile: Bs[kk][j] = WcatP[j][k0+kk]
#pragma unroll
        for (int i = 0; i < 2; i++) {
            int idx = tid + i * 256;
            int j  = idx >> 3;
            int c4 = idx & 7;
            float4 v = *(const float4*)&g_WcatP[(size_t)j * 256 + k0 + c4 * 4];
            Bs[c4 * 4 + 0][j] = v.x;
            Bs[c4 * 4 + 1][j] = v.y;
            Bs[c4 * 4 + 2][j] = v.z;
            Bs[c4 * 4 + 3][j] = v.w;
        }
        __syncthreads();

#pragma unroll
        for (int kk = 0; kk < 32; kk++) {
            float4 a  = *(float4*)&As[kk][ty * 4];
            float4 bb = *(float4*)&Bs[kk][tx * 4];
            float av[4] = {a.x, a.y, a.z, a.w};
            float bv[4] = {bb.x, bb.y, bb.z, bb.w};
#pragma unroll
            for (int i = 0; i < 4; i++)
#pragma unroll
                for (int j = 0; j < 4; j++)
                    acc[i][j] += av[i] * bv[j];
        }
        __syncthreads();
    }

    float4 bb = *(const float4*)&g_bcatP[tx * 4];
    float bv[4] = {bb.x, bb.y, bb.z, bb.w};
#pragma unroll
    for (int i = 0; i < 4; i++) {
        int m = m0 + ty * 4 + i;
        float4 o;
        o.x = acc[i][0] + bv[0];
        o.y = acc[i][1] + bv[1];
        o.z = acc[i][2] + bv[2];
        o.w = acc[i][3] + bv[3];
        *(float4*)&g_dots[(size_t)m * 64 + tx * 4] = o;
    }
}

// ---------------------------------------------------------------------------
// Kernel 3: coords + softmax.  16 lanes per query, 16 queries per block.
// ---------------------------------------------------------------------------
__global__ __launch_bounds__(256) void coord_kernel(const float* __restrict__ base_ref)
{
    const int tid  = threadIdx.x;
    const int w    = tid >> 5;
    const int lane = tid & 31;
    const int sub  = lane >> 4;       // 0/1 within warp
    const int p    = lane & 15;
    const int qidx = blockIdx.x * 16 + w * 2 + sub;

    const int b = qidx >> 13;         // Qn = 8192

    const float* dots = &g_dots[(size_t)qidx * 64];

    // softmax over 16 attn logits (within 16-lane group)
    float logit = dots[36 + p];
    float m = logit;
#pragma unroll
    for (int o = 8; o; o >>= 1)
        m = fmaxf(m, __shfl_xor_sync(0xffffffffu, m, o));
    float e = expf(logit - m);
    float esum = e;
#pragma unroll
    for (int o = 8; o; o >>= 1)
        esum += __shfl_xor_sync(0xffffffffu, esum, o);
    float wattn = e / esum;

    const int l  = p >> 3;
    const int pp = p & 7;
    const int Wl = l ? W1 : W0;
    const int Hl = l ? H1 : H0;

    float bx = base_ref[(b * Lv + l) * 2 + 0];
    float by = base_ref[(b * Lv + l) * 2 + 1];
    bx = fminf(fmaxf(bx, EPSV), 1.f - EPSV);
    by = fminf(fmaxf(by, EPSV), 1.f - EPSV);
    float lbx = logf(bx / (1.f - bx));
    float lby = logf(by / (1.f - by));
    float rx = 1.f / (1.f + expf(-(lbx + dots[l * 2 + 0])));
    float ry = 1.f / (1.f + expf(-(lby + dots[l * 2 + 1])));

    float ox = dots[4 + l * 16 + pp * 2 + 0];
    float oy = dots[4 + l * 16 + pp * 2 + 1];
    float lx = rx + ox / (float)Wl;
    float ly = ry + oy / (float)Hl;
    if (l == 1) ly = ly - floorf(ly);   // jnp.remainder(ly, 1.0)

    float x = lx * (float)Wl - 0.5f;
    float y = ly * (float)Hl - 0.5f;
    x = fminf(fmaxf(x, 0.f), (float)(Wl - 1));
    y = fminf(fmaxf(y, 0.f), (float)(Hl - 1));
    float x0f = floorf(x), y0f = floorf(y);
    int x0 = (int)x0f, y0 = (int)y0f;
    int x1 = min(x0 + 1, Wl - 1);
    int y1 = min(y0 + 1, Hl - 1);
    int base = b * Hl * Wl * Dm;

    int4 off;
    off.x = base + (y0 * Wl + x0) * Dm;
    off.y = base + (y0 * Wl + x1) * Dm;
    off.z = base + (y1 * Wl + x0) * Dm;
    off.w = base + (y1 * Wl + x1) * Dm;
    g_soff[qidx * 16 + p] = off;
    g_swt [qidx * 16 + p] = make_float4(x - x0f, y - y0f, wattn, 0.f);
}

// ---------------------------------------------------------------------------
// Kernel 4: gather. One query per block; warp w handles points w and w+8.
// ---------------------------------------------------------------------------
__global__ __launch_bounds__(256) void gather_kernel()
{
    __shared__ int4   soff[16];
    __shared__ float4 swt[16];
    __shared__ float  wacc[8][264];

    const int qidx = blockIdx.x;
    const int tid  = threadIdx.x;
    const int w    = tid >> 5;
    const int lane = tid & 31;

    if (tid < 16) {
        soff[tid] = g_soff[qidx * 16 + tid];
        swt[tid]  = g_swt [qidx * 16 + tid];
    }
    __syncthreads();

    float4 accLo = make_float4(0.f, 0.f, 0.f, 0.f);
    float4 accHi = make_float4(0.f, 0.f, 0.f, 0.f);

#pragma unroll
    for (int t = 0; t < 2; t++) {
        const int p = w + t * 8;
        const int4   o  = soff[p];
        const float4 wt = swt[p];
        const float* mp = (p < 8) ? g_map0 : g_map1;
        const float wx = wt.x, wy = wt.y, wz = wt.z;

#pragma unroll
        for (int h = 0; h < 2; h++) {
            const int co = h * 128 + lane * 4;
            float4 v00 = __ldg((const float4*)(mp + o.x + co));
            float4 v01 = __ldg((const float4*)(mp + o.y + co));
            float4 v10 = __ldg((const float4*)(mp + o.z + co));
            float4 v11 = __ldg((const float4*)(mp + o.w + co));
            float4* acc = h ? &accHi : &accLo;

            float top, bot, r;
            top = v00.x + wx * (v01.x - v00.x);
            bot = v10.x + wx * (v11.x - v10.x);
            r = top + wy * (bot - top);
            acc->x += wz * r;
            top = v00.y + wx * (v01.y - v00.y);
            bot = v10.y + wx * (v11.y - v10.y);
            r = top + wy * (bot - top);
            acc->y += wz * r;
            top = v00.z + wx * (v01.z - v00.z);
            bot = v10.z + wx * (v11.z - v10.z);
            r = top + wy * (bot - top);
            acc->z += wz * r;
            top = v00.w + wx * (v01.w - v00.w);
            bot = v10.w + wx * (v11.w - v10.w);
            r = top + wy * (bot - top);
            acc->w += wz * r;
        }
    }

    *(float4*)&wacc[w][lane * 4]       = accLo;
    *(float4*)&wacc[w][128 + lane * 4] = accHi;
    __syncthreads();

    float s = 0.f;
#pragma unroll
    for (int ww = 0; ww < 8; ww++)
        s += wacc[ww][tid];
    g_pre[(size_t)qidx * 256 + tid] = s;
}

// ---------------------------------------------------------------------------
// Kernel 5: C = g_pre(M,256) @ Wout(256,256) + bout.  BM=BN=64, BK=32, 4x4/thr
// ---------------------------------------------------------------------------
#define BM 64
#define BN 64
#define BK 32

__global__ __launch_bounds__(256) void gemm_kernel(
    const float* __restrict__ Wt, const float* __restrict__ bias,
    float* __restrict__ C)
{
    __shared__ float As[BK][BM];
    __shared__ float Bs[BK][BN];

    const int tid = threadIdx.x;
    const int m0 = blockIdx.y * BM;
    const int n0 = blockIdx.x * BN;
    const int tx = tid & 15;
    const int ty = tid >> 4;

    float acc[4][4] = {};

    for (int k0 = 0; k0 < 256; k0 += BK) {
#pragma unroll
        for (int i = 0; i < 2; i++) {
            int idx = tid + i * 256;
            int r  = idx >> 3;
            int c4 = idx & 7;
            float4 v = *(const float4*)&g_pre[(size_t)(m0 + r) * 256 + k0 + c4 * 4];
            As[c4 * 4 + 0][r] = v.x;
            As[c4 * 4 + 1][r] = v.y;
            As[c4 * 4 + 2][r] = v.z;
            As[c4 * 4 + 3][r] = v.w;
        }
#pragma unroll
        for (int i = 0; i < 2; i++) {
            int idx = tid + i * 256;
            int r  = idx >> 4;
            int c4 = idx & 15;
            *(float4*)&Bs[r][c4 * 4] =
                *(const float4*)&Wt[(size_t)(k0 + r) * 256 + n0 + c4 * 4];
        }
        __syncthreads();

#pragma unroll
        for (int kk = 0; kk < BK; kk++) {
            float4 a  = *(float4*)&As[kk][ty * 4];
            float4 bb = *(float4*)&Bs[kk][tx * 4];
            float av[4] = {a.x, a.y, a.z, a.w};
            float bv[4] = {bb.x, bb.y, bb.z, bb.w};
#pragma unroll
            for (int i = 0; i < 4; i++)
#pragma unroll
                for (int j = 0; j < 4; j++)
                    acc[i][j] += av[i] * bv[j];
        }
        __syncthreads();
    }

    float4 bb = *(const float4*)&bias[n0 + tx * 4];
    float bv[4] = {bb.x, bb.y, bb.z, bb.w};
#pragma unroll
    for (int i = 0; i < 4; i++) {
        int m = m0 + ty * 4 + i;
        float4 o;
        o.x = acc[i][0] + bv[0];
        o.y = acc[i][1] + bv[1];
        o.z = acc[i][2] + bv[2];
        o.w = acc[i][3] + bv[3];
        *(float4*)&C[(size_t)m * 256 + n0 + tx * 4] = o;
    }
}

// ---------------------------------------------------------------------------
extern "C" void kernel_launch(void* const* d_in, const int* in_sizes, int n_in,
                              void* d_out, int out_size)
{
    const float* q        = (const float*)d_in[0];
    const float* map0     = (const float*)d_in[1];
    const float* map1     = (const float*)d_in[2];
    const float* base_ref = (const float*)d_in[3];
    const float* Wrd      = (const float*)d_in[4];
    const float* brd      = (const float*)d_in[5];
    const float* Woff     = (const float*)d_in[6];
    const float* boff     = (const float*)d_in[7];
    const float* Wattn    = (const float*)d_in[8];
    const float* battn    = (const float*)d_in[9];
    const float* Wout     = (const float*)d_in[10];
    const float* bout     = (const float*)d_in[11];
    float* out = (float*)d_out;

    pack_weights_kernel<<<64, 256>>>(Wrd, brd, Woff, boff, Wattn, battn);

    transpose_kernel<<<dim3((H0 * W0) / 32, Dm / 32, Bn), dim3(32, 8)>>>(map0, H0 * W0, 0);
    transpose_kernel<<<dim3((H1 * W1) / 32, Dm / 32, Bn), dim3(32, 8)>>>(map1, H1 * W1, 1);

    proj_gemm_kernel<<<NQ / 64, 256>>>(q);

    coord_kernel<<<NQ / 16, 256>>>(base_ref);

    gather_kernel<<<NQ, 256>>>();

    gemm_kernel<<<dim3(256 / BN, NQ / BM), 256>>>(Wout, bout, out);
}

// round 4
// speedup vs baseline: 4.5163x; 1.0006x over previous
#include <cuda_runtime.h>
#include <math.h>

#define Bn 4
#define Qn 8192
#define Dm 256
#define Lv 2
#define Pp 8
#define H0 128
#define W0 128
#define H1 64
#define W1 64
#define EPSV 1e-5f
#define NQ (Bn * Qn)          // 32768 total queries

// Scratch (device globals — no allocations allowed)
__device__ float  g_map0[Bn * H0 * W0 * Dm];   // (B, H*W, D) HWC fp32
__device__ float  g_map1[Bn * H1 * W1 * Dm];
__device__ float  g_pre [NQ * Dm];             // pre-Wout accumulator
__device__ float  g_WcatP[64 * 256];           // packed transposed weights (52 used, zero pad)
__device__ float  g_bcatP[64];
__device__ float  g_dots[NQ * 64];             // projection outputs per query
__device__ int4   g_soff[NQ * 16];             // per (q,p): 4 corner element-offsets
__device__ float4 g_swt [NQ * 16];             // per (q,p): wx, wy, attn_w, 0

// ---------------------------------------------------------------------------
// Kernel 0: pack weights transposed into 64x256 (rows 52..63 zero).
// j: 0..3 = Wrd cols, 4..35 = Woff cols, 36..51 = Wattn cols
// ---------------------------------------------------------------------------
__global__ __launch_bounds__(256) void pack_weights_kernel(
    const float* __restrict__ Wrd,  const float* __restrict__ brd,
    const float* __restrict__ Woff, const float* __restrict__ boff,
    const float* __restrict__ Wattn,const float* __restrict__ battn)
{
    int j = blockIdx.x;
    int k = threadIdx.x;
    float v = 0.f, bv = 0.f;
    if (j < 4)       { v = Wrd  [k * 4  + j];      bv = brd  [j]; }
    else if (j < 36) { v = Woff [k * 32 + (j-4)];  bv = boff [j-4]; }
    else if (j < 52) { v = Wattn[k * 16 + (j-36)]; bv = battn[j-36]; }
    g_WcatP[j * 256 + k] = v;
    if (k == 0) g_bcatP[j] = bv;
}

// ---------------------------------------------------------------------------
// Kernel 1: (B, D, HW) -> (B, HW, D) tiled transpose
// ---------------------------------------------------------------------------
__global__ __launch_bounds__(256) void transpose_kernel(
    const float* __restrict__ in, int HW, int level)
{
    __shared__ float tile[32][33];
    float* out = level ? g_map1 : g_map0;

    int hw0 = blockIdx.x * 32;
    int d0  = blockIdx.y * 32;
    int b   = blockIdx.z;
    int tx = threadIdx.x;
    int ty = threadIdx.y;

    const float* inb = in + (size_t)b * Dm * HW;
    float* outb = out + (size_t)b * HW * Dm;

#pragma unroll
    for (int i = 0; i < 4; i++) {
        int d = d0 + ty + 8 * i;
        tile[ty + 8 * i][tx] = inb[(size_t)d * HW + hw0 + tx];
    }
    __syncthreads();
#pragma unroll
    for (int i = 0; i < 4; i++) {
        int hw = hw0 + ty + 8 * i;
        outb[(size_t)hw * Dm + d0 + tx] = tile[tx][ty + 8 * i];
    }
}

// ---------------------------------------------------------------------------
// Kernel 2: projection GEMM  g_dots[NQ][64] = q(NQ x 256) @ WcatP^T + bcatP
// BM=64, BN=64, BK=32, 4x4 microtile
// ---------------------------------------------------------------------------
__global__ __launch_bounds__(256) void proj_gemm_kernel(const float* __restrict__ q)
{
    __shared__ float As[32][64];
    __shared__ float Bs[32][64];

    const int tid = threadIdx.x;
    const int m0 = blockIdx.x * 64;
    const int tx = tid & 15;
    const int ty = tid >> 4;

    float acc[4][4] = {};

    for (int k0 = 0; k0 < 256; k0 += 32) {
        // A tile: 64 rows x 32 k (from q), store k-major
#pragma unroll
        for (int i = 0; i < 2; i++) {
            int idx = tid + i * 256;
            int r  = idx >> 3;
            int c4 = idx & 7;
            float4 v = *(const float4*)&q[(size_t)(m0 + r) * 256 + k0 + c4 * 4];
            As[c4 * 4 + 0][r] = v.x;
            As[c4 * 4 + 1][r] = v.y;
            As[c4 * 4 + 2][r] = v.z;
            As[c4 * 4 + 3][r] = v.w;
        }
        // B tile: Bs[kk][j] = WcatP[j][k0+kk]
#pragma unroll
        for (int i = 0; i < 2; i++) {
            int idx = tid + i * 256;
            int j  = idx >> 3;
            int c4 = idx & 7;
            float4 v = *(const float4*)&g_WcatP[(size_t)j * 256 + k0 + c4 * 4];
            Bs[c4 * 4 + 0][j] = v.x;
            Bs[c4 * 4 + 1][j] = v.y;
            Bs[c4 * 4 + 2][j] = v.z;
            Bs[c4 * 4 + 3][j] = v.w;
        }
        __syncthreads();

#pragma unroll
        for (int kk = 0; kk < 32; kk++) {
            float4 a  = *(float4*)&As[kk][ty * 4];
            float4 bb = *(float4*)&Bs[kk][tx * 4];
            float av[4] = {a.x, a.y, a.z, a.w};
            float bv[4] = {bb.x, bb.y, bb.z, bb.w};
#pragma unroll
            for (int i = 0; i < 4; i++)
#pragma unroll
                for (int j = 0; j < 4; j++)
                    acc[i][j] += av[i] * bv[j];
        }
        __syncthreads();
    }

    float4 bb = *(const float4*)&g_bcatP[tx * 4];
    float bv[4] = {bb.x, bb.y, bb.z, bb.w};
#pragma unroll
    for (int i = 0; i < 4; i++) {
        int m = m0 + ty * 4 + i;
        float4 o;
        o.x = acc[i][0] + bv[0];
        o.y = acc[i][1] + bv[1];
        o.z = acc[i][2] + bv[2];
        o.w = acc[i][3] + bv[3];
        *(float4*)&g_dots[(size_t)m * 64 + tx * 4] = o;
    }
}

// ---------------------------------------------------------------------------
// Kernel 3: coords + softmax.  16 lanes per query, 16 queries per block.
// ---------------------------------------------------------------------------
__global__ __launch_bounds__(256) void coord_kernel(const float* __restrict__ base_ref)
{
    const int tid  = threadIdx.x;
    const int w    = tid >> 5;
    const int lane = tid & 31;
    const int sub  = lane >> 4;       // 0/1 within warp
    const int p    = lane & 15;
    const int qidx = blockIdx.x * 16 + w * 2 + sub;

    const int b = qidx >> 13;         // Qn = 8192

    const float* dots = &g_dots[(size_t)qidx * 64];

    // softmax over 16 attn logits (within 16-lane group)
    float logit = dots[36 + p];
    float m = logit;
#pragma unroll
    for (int o = 8; o; o >>= 1)
        m = fmaxf(m, __shfl_xor_sync(0xffffffffu, m, o));
    float e = expf(logit - m);
    float esum = e;
#pragma unroll
    for (int o = 8; o; o >>= 1)
        esum += __shfl_xor_sync(0xffffffffu, esum, o);
    float wattn = e / esum;

    const int l  = p >> 3;
    const int pp = p & 7;
    const int Wl = l ? W1 : W0;
    const int Hl = l ? H1 : H0;

    float bx = base_ref[(b * Lv + l) * 2 + 0];
    float by = base_ref[(b * Lv + l) * 2 + 1];
    bx = fminf(fmaxf(bx, EPSV), 1.f - EPSV);
    by = fminf(fmaxf(by, EPSV), 1.f - EPSV);
    float lbx = logf(bx / (1.f - bx));
    float lby = logf(by / (1.f - by));
    float rx = 1.f / (1.f + expf(-(lbx + dots[l * 2 + 0])));
    float ry = 1.f / (1.f + expf(-(lby + dots[l * 2 + 1])));

    float ox = dots[4 + l * 16 + pp * 2 + 0];
    float oy = dots[4 + l * 16 + pp * 2 + 1];
    float lx = rx + ox / (float)Wl;
    float ly = ry + oy / (float)Hl;
    if (l == 1) ly = ly - floorf(ly);   // jnp.remainder(ly, 1.0)

    float x = lx * (float)Wl - 0.5f;
    float y = ly * (float)Hl - 0.5f;
    x = fminf(fmaxf(x, 0.f), (float)(Wl - 1));
    y = fminf(fmaxf(y, 0.f), (float)(Hl - 1));
    float x0f = floorf(x), y0f = floorf(y);
    int x0 = (int)x0f, y0 = (int)y0f;
    int x1 = min(x0 + 1, Wl - 1);
    int y1 = min(y0 + 1, Hl - 1);
    int base = b * Hl * Wl * Dm;

    int4 off;
    off.x = base + (y0 * Wl + x0) * Dm;
    off.y = base + (y0 * Wl + x1) * Dm;
    off.z = base + (y1 * Wl + x0) * Dm;
    off.w = base + (y1 * Wl + x1) * Dm;
    g_soff[qidx * 16 + p] = off;
    g_swt [qidx * 16 + p] = make_float4(x - x0f, y - y0f, wattn, 0.f);
}

// ---------------------------------------------------------------------------
// Kernel 4: gather. One query per block; warp w handles points w and w+8.
// ---------------------------------------------------------------------------
__global__ __launch_bounds__(256) void gather_kernel()
{
    __shared__ int4   soff[16];
    __shared__ float4 swt[16];
    __shared__ float  wacc[8][264];

    const int qidx = blockIdx.x;
    const int tid  = threadIdx.x;
    const int w    = tid >> 5;
    const int lane = tid & 31;

    if (tid < 16) {
        soff[tid] = g_soff[qidx * 16 + tid];
        swt[tid]  = g_swt [qidx * 16 + tid];
    }
    __syncthreads();

    float4 accLo = make_float4(0.f, 0.f, 0.f, 0.f);
    float4 accHi = make_float4(0.f, 0.f, 0.f, 0.f);

#pragma unroll
    for (int t = 0; t < 2; t++) {
        const int p = w + t * 8;
        const int4   o  = soff[p];
        const float4 wt = swt[p];
        const float* mp = (p < 8) ? g_map0 : g_map1;
        const float wx = wt.x, wy = wt.y, wz = wt.z;

#pragma unroll
        for (int h = 0; h < 2; h++) {
            const int co = h * 128 + lane * 4;
            float4 v00 = __ldg((const float4*)(mp + o.x + co));
            float4 v01 = __ldg((const float4*)(mp + o.y + co));
            float4 v10 = __ldg((const float4*)(mp + o.z + co));
            float4 v11 = __ldg((const float4*)(mp + o.w + co));
            float4* acc = h ? &accHi : &accLo;

            float top, bot, r;
            top = v00.x + wx * (v01.x - v00.x);
            bot = v10.x + wx * (v11.x - v10.x);
            r = top + wy * (bot - top);
            acc->x += wz * r;
            top = v00.y + wx * (v01.y - v00.y);
            bot = v10.y + wx * (v11.y - v10.y);
            r = top + wy * (bot - top);
            acc->y += wz * r;
            top = v00.z + wx * (v01.z - v00.z);
            bot = v10.z + wx * (v11.z - v10.z);
            r = top + wy * (bot - top);
            acc->z += wz * r;
            top = v00.w + wx * (v01.w - v00.w);
            bot = v10.w + wx * (v11.w - v10.w);
            r = top + wy * (bot - top);
            acc->w += wz * r;
        }
    }

    *(float4*)&wacc[w][lane * 4]       = accLo;
    *(float4*)&wacc[w][128 + lane * 4] = accHi;
    __syncthreads();

    float s = 0.f;
#pragma unroll
    for (int ww = 0; ww < 8; ww++)
        s += wacc[ww][tid];
    g_pre[(size_t)qidx * 256 + tid] = s;
}

// ---------------------------------------------------------------------------
// Kernel 5: C = g_pre(M,256) @ Wout(256,256) + bout.  BM=BN=64, BK=32, 4x4/thr
// ---------------------------------------------------------------------------
#define BM 64
#define BN 64
#define BK 32

__global__ __launch_bounds__(256) void gemm_kernel(
    const float* __restrict__ Wt, const float* __restrict__ bias,
    float* __restrict__ C)
{
    __shared__ float As[BK][BM];
    __shared__ float Bs[BK][BN];

    const int tid = threadIdx.x;
    const int m0 = blockIdx.y * BM;
    const int n0 = blockIdx.x * BN;
    const int tx = tid & 15;
    const int ty = tid >> 4;

    float acc[4][4] = {};

    for (int k0 = 0; k0 < 256; k0 += BK) {
#pragma unroll
        for (int i = 0; i < 2; i++) {
            int idx = tid + i * 256;
            int r  = idx >> 3;
            int c4 = idx & 7;
            float4 v = *(const float4*)&g_pre[(size_t)(m0 + r) * 256 + k0 + c4 * 4];
            As[c4 * 4 + 0][r] = v.x;
            As[c4 * 4 + 1][r] = v.y;
            As[c4 * 4 + 2][r] = v.z;
            As[c4 * 4 + 3][r] = v.w;
        }
#pragma unroll
        for (int i = 0; i < 2; i++) {
            int idx = tid + i * 256;
            int r  = idx >> 4;
            int c4 = idx & 15;
            *(float4*)&Bs[r][c4 * 4] =
                *(const float4*)&Wt[(size_t)(k0 + r) * 256 + n0 + c4 * 4];
        }
        __syncthreads();

#pragma unroll
        for (int kk = 0; kk < BK; kk++) {
            float4 a  = *(float4*)&As[kk][ty * 4];
            float4 bb = *(float4*)&Bs[kk][tx * 4];
            float av[4] = {a.x, a.y, a.z, a.w};
            float bv[4] = {bb.x, bb.y, bb.z, bb.w};
#pragma unroll
            for (int i = 0; i < 4; i++)
#pragma unroll
                for (int j = 0; j < 4; j++)
                    acc[i][j] += av[i] * bv[j];
        }
        __syncthreads();
    }

    float4 bb = *(const float4*)&bias[n0 + tx * 4];
    float bv[4] = {bb.x, bb.y, bb.z, bb.w};
#pragma unroll
    for (int i = 0; i < 4; i++) {
        int m = m0 + ty * 4 + i;
        float4 o;
        o.x = acc[i][0] + bv[0];
        o.y = acc[i][1] + bv[1];
        o.z = acc[i][2] + bv[2];
        o.w = acc[i][3] + bv[3];
        *(float4*)&C[(size_t)m * 256 + n0 + tx * 4] = o;
    }
}

// ---------------------------------------------------------------------------
extern "C" void kernel_launch(void* const* d_in, const int* in_sizes, int n_in,
                              void* d_out, int out_size)
{
    const float* q        = (const float*)d_in[0];
    const float* map0     = (const float*)d_in[1];
    const float* map1     = (const float*)d_in[2];
    const float* base_ref = (const float*)d_in[3];
    const float* Wrd      = (const float*)d_in[4];
    const float* brd      = (const float*)d_in[5];
    const float* Woff     = (const float*)d_in[6];
    const float* boff     = (const float*)d_in[7];
    const float* Wattn    = (const float*)d_in[8];
    const float* battn    = (const float*)d_in[9];
    const float* Wout     = (const float*)d_in[10];
    const float* bout     = (const float*)d_in[11];
    float* out = (float*)d_out;

    pack_weights_kernel<<<64, 256>>>(Wrd, brd, Woff, boff, Wattn, battn);

    transpose_kernel<<<dim3((H0 * W0) / 32, Dm / 32, Bn), dim3(32, 8)>>>(map0, H0 * W0, 0);
    transpose_kernel<<<dim3((H1 * W1) / 32, Dm / 32, Bn), dim3(32, 8)>>>(map1, H1 * W1, 1);

    proj_gemm_kernel<<<NQ / 64, 256>>>(q);

    coord_kernel<<<NQ / 16, 256>>>(base_ref);

    gather_kernel<<<NQ, 256>>>();

    gemm_kernel<<<dim3(256 / BN, NQ / BM), 256>>>(Wout, bout, out);
}

// round 5
// speedup vs baseline: 5.1549x; 1.1414x over previous
#include <cuda_runtime.h>
#include <cuda_fp16.h>
#include <math.h>

#define Bn 4
#define Qn 8192
#define Dm 256
#define Lv 2
#define Pp 8
#define H0 128
#define W0 128
#define H1 64
#define W1 64
#define EPSV 1e-5f
#define NQ (Bn * Qn)          // 32768 total queries

// Scratch (device globals — no allocations allowed)
__device__ __half g_map0[Bn * H0 * W0 * Dm];   // (B, H*W, D) HWC fp16
__device__ __half g_map1[Bn * H1 * W1 * Dm];
__device__ float  g_pre [NQ * Dm];             // pre-Wout accumulator
__device__ float  g_WcatP[64 * 256];           // packed transposed weights (52 used, zero pad)
__device__ float  g_bcatP[64];
__device__ float  g_dots[NQ * 64];             // projection outputs per query
__device__ int4   g_soff[NQ * 16];             // per (q,p): 4 corner element-offsets
__device__ float4 g_swt [NQ * 16];             // per (q,p): wx, wy, attn_w, 0

// ---------------------------------------------------------------------------
// Kernel 0: pack weights transposed into 64x256 (rows 52..63 zero).
// ---------------------------------------------------------------------------
__global__ __launch_bounds__(256) void pack_weights_kernel(
    const float* __restrict__ Wrd,  const float* __restrict__ brd,
    const float* __restrict__ Woff, const float* __restrict__ boff,
    const float* __restrict__ Wattn,const float* __restrict__ battn)
{
    int j = blockIdx.x;
    int k = threadIdx.x;
    float v = 0.f, bv = 0.f;
    if (j < 4)       { v = Wrd  [k * 4  + j];      bv = brd  [j]; }
    else if (j < 36) { v = Woff [k * 32 + (j-4)];  bv = boff [j-4]; }
    else if (j < 52) { v = Wattn[k * 16 + (j-36)]; bv = battn[j-36]; }
    g_WcatP[j * 256 + k] = v;
    if (k == 0) g_bcatP[j] = bv;
}

// ---------------------------------------------------------------------------
// Kernel 1: (B, D, HW) -> (B, HW, D) tiled transpose, fp32 -> fp16.
// Tile: 64 d x 32 hw.  grid = (HW/32, Dm/64, Bn), block = 256
// ---------------------------------------------------------------------------
__global__ __launch_bounds__(256) void transpose_kernel(
    const float* __restrict__ in, int HW, int level)
{
    __shared__ float tile[64][33];
    __half* out = level ? g_map1 : g_map0;

    const int hw0 = blockIdx.x * 32;
    const int d0  = blockIdx.y * 64;
    const int b   = blockIdx.z;
    const int tid  = threadIdx.x;
    const int tx   = tid & 31;
    const int ty   = tid >> 5;     // 0..7

    const float* inb = in + (size_t)b * Dm * HW;
    __half* outb = out + (size_t)b * HW * Dm;

#pragma unroll
    for (int i = 0; i < 8; i++) {
        int d = d0 + ty + 8 * i;
        tile[ty + 8 * i][tx] = inb[(size_t)d * HW + hw0 + tx];
    }
    __syncthreads();

    // warp ty writes hw rows ty, ty+8, ty+16, ty+24; lane = d-pair 0..31
#pragma unroll
    for (int i = 0; i < 4; i++) {
        int hw = ty + 8 * i;
        __half2 v = __floats2half2_rn(tile[2 * tx][hw], tile[2 * tx + 1][hw]);
        ((__half2*)(outb + (size_t)(hw0 + hw) * Dm + d0))[tx] = v;
    }
}

// ---------------------------------------------------------------------------
// Kernel 2: projection GEMM  g_dots[NQ][64] = q(NQ x 256) @ WcatP^T + bcatP
// BM=128, BN=64, BK=32, 8x4 microtile, smem double-buffered.
// ---------------------------------------------------------------------------
#define PBM 128
#define PBN 64
#define PBK 32

__global__ __launch_bounds__(256) void proj_gemm_kernel(const float* __restrict__ q)
{
    __shared__ float As[2][PBK][PBM];
    __shared__ float Bs[2][PBK][PBN];

    const int tid = threadIdx.x;
    const int m0 = blockIdx.x * PBM;
    const int tx = tid & 15;       // N: tx*4
    const int ty = tid >> 4;       // M: ty*8

    float acc[8][4] = {};
    float4 ra[4], rb[2];

    // ---- load tile 0 into regs ----
#pragma unroll
    for (int i = 0; i < 4; i++) {
        int idx = tid + i * 256;
        int r = idx >> 3, c4 = idx & 7;
        ra[i] = *(const float4*)&q[(size_t)(m0 + r) * 256 + c4 * 4];
    }
#pragma unroll
    for (int i = 0; i < 2; i++) {
        int idx = tid + i * 256;
        int j = idx >> 3, c4 = idx & 7;
        rb[i] = *(const float4*)&g_WcatP[(size_t)j * 256 + c4 * 4];
    }
    // ---- store buf 0 ----
#pragma unroll
    for (int i = 0; i < 4; i++) {
        int idx = tid + i * 256;
        int r = idx >> 3, c4 = idx & 7;
        As[0][c4 * 4 + 0][r] = ra[i].x;
        As[0][c4 * 4 + 1][r] = ra[i].y;
        As[0][c4 * 4 + 2][r] = ra[i].z;
        As[0][c4 * 4 + 3][r] = ra[i].w;
    }
#pragma unroll
    for (int i = 0; i < 2; i++) {
        int idx = tid + i * 256;
        int j = idx >> 3, c4 = idx & 7;
        Bs[0][c4 * 4 + 0][j] = rb[i].x;
        Bs[0][c4 * 4 + 1][j] = rb[i].y;
        Bs[0][c4 * 4 + 2][j] = rb[i].z;
        Bs[0][c4 * 4 + 3][j] = rb[i].w;
    }
    __syncthreads();

    int buf = 0;
#pragma unroll
    for (int it = 0; it < 8; it++) {
        const int k0n = (it + 1) * PBK;
        if (it < 7) {
            // issue next tile's global loads early (overlap with compute)
#pragma unroll
            for (int i = 0; i < 4; i++) {
                int idx = tid + i * 256;
                int r = idx >> 3, c4 = idx & 7;
                ra[i] = *(const float4*)&q[(size_t)(m0 + r) * 256 + k0n + c4 * 4];
            }
#pragma unroll
            for (int i = 0; i < 2; i++) {
                int idx = tid + i * 256;
                int j = idx >> 3, c4 = idx & 7;
                rb[i] = *(const float4*)&g_WcatP[(size_t)j * 256 + k0n + c4 * 4];
            }
        }

#pragma unroll
        for (int kk = 0; kk < PBK; kk++) {
            float4 a0 = *(float4*)&As[buf][kk][ty * 8];
            float4 a1 = *(float4*)&As[buf][kk][ty * 8 + 4];
            float4 bb = *(float4*)&Bs[buf][kk][tx * 4];
            float av[8] = {a0.x, a0.y, a0.z, a0.w, a1.x, a1.y, a1.z, a1.w};
            float bv[4] = {bb.x, bb.y, bb.z, bb.w};
#pragma unroll
            for (int i = 0; i < 8; i++)
#pragma unroll
                for (int j = 0; j < 4; j++)
                    acc[i][j] += av[i] * bv[j];
        }

        if (it < 7) {
            int nb = buf ^ 1;
#pragma unroll
            for (int i = 0; i < 4; i++) {
                int idx = tid + i * 256;
                int r = idx >> 3, c4 = idx & 7;
                As[nb][c4 * 4 + 0][r] = ra[i].x;
                As[nb][c4 * 4 + 1][r] = ra[i].y;
                As[nb][c4 * 4 + 2][r] = ra[i].z;
                As[nb][c4 * 4 + 3][r] = ra[i].w;
            }
#pragma unroll
            for (int i = 0; i < 2; i++) {
                int idx = tid + i * 256;
                int j = idx >> 3, c4 = idx & 7;
                Bs[nb][c4 * 4 + 0][j] = rb[i].x;
                Bs[nb][c4 * 4 + 1][j] = rb[i].y;
                Bs[nb][c4 * 4 + 2][j] = rb[i].z;
                Bs[nb][c4 * 4 + 3][j] = rb[i].w;
            }
            __syncthreads();
            buf = nb;
        }
    }

    float4 bb = *(const float4*)&g_bcatP[tx * 4];
    float bv[4] = {bb.x, bb.y, bb.z, bb.w};
#pragma unroll
    for (int i = 0; i < 8; i++) {
        int m = m0 + ty * 8 + i;
        float4 o;
        o.x = acc[i][0] + bv[0];
        o.y = acc[i][1] + bv[1];
        o.z = acc[i][2] + bv[2];
        o.w = acc[i][3] + bv[3];
        *(float4*)&g_dots[(size_t)m * 64 + tx * 4] = o;
    }
}

// ---------------------------------------------------------------------------
// Kernel 3: coords + softmax.  16 lanes per query, 16 queries per block.
// ---------------------------------------------------------------------------
__global__ __launch_bounds__(256) void coord_kernel(const float* __restrict__ base_ref)
{
    const int tid  = threadIdx.x;
    const int w    = tid >> 5;
    const int lane = tid & 31;
    const int sub  = lane >> 4;
    const int p    = lane & 15;
    const int qidx = blockIdx.x * 16 + w * 2 + sub;

    const int b = qidx >> 13;         // Qn = 8192

    const float* dots = &g_dots[(size_t)qidx * 64];

    float logit = dots[36 + p];
    float m = logit;
#pragma unroll
    for (int o = 8; o; o >>= 1)
        m = fmaxf(m, __shfl_xor_sync(0xffffffffu, m, o));
    float e = expf(logit - m);
    float esum = e;
#pragma unroll
    for (int o = 8; o; o >>= 1)
        esum += __shfl_xor_sync(0xffffffffu, esum, o);
    float wattn = e / esum;

    const int l  = p >> 3;
    const int pp = p & 7;
    const int Wl = l ? W1 : W0;
    const int Hl = l ? H1 : H0;

    float bx = base_ref[(b * Lv + l) * 2 + 0];
    float by = base_ref[(b * Lv + l) * 2 + 1];
    bx = fminf(fmaxf(bx, EPSV), 1.f - EPSV);
    by = fminf(fmaxf(by, EPSV), 1.f - EPSV);
    float lbx = logf(bx / (1.f - bx));
    float lby = logf(by / (1.f - by));
    float rx = 1.f / (1.f + expf(-(lbx + dots[l * 2 + 0])));
    float ry = 1.f / (1.f + expf(-(lby + dots[l * 2 + 1])));

    float ox = dots[4 + l * 16 + pp * 2 + 0];
    float oy = dots[4 + l * 16 + pp * 2 + 1];
    float lx = rx + ox / (float)Wl;
    float ly = ry + oy / (float)Hl;
    if (l == 1) ly = ly - floorf(ly);

    float x = lx * (float)Wl - 0.5f;
    float y = ly * (float)Hl - 0.5f;
    x = fminf(fmaxf(x, 0.f), (float)(Wl - 1));
    y = fminf(fmaxf(y, 0.f), (float)(Hl - 1));
    float x0f = floorf(x), y0f = floorf(y);
    int x0 = (int)x0f, y0 = (int)y0f;
    int x1 = min(x0 + 1, Wl - 1);
    int y1 = min(y0 + 1, Hl - 1);
    int base = b * Hl * Wl * Dm;

    int4 off;
    off.x = base + (y0 * Wl + x0) * Dm;
    off.y = base + (y0 * Wl + x1) * Dm;
    off.z = base + (y1 * Wl + x0) * Dm;
    off.w = base + (y1 * Wl + x1) * Dm;
    g_soff[qidx * 16 + p] = off;
    g_swt [qidx * 16 + p] = make_float4(x - x0f, y - y0f, wattn, 0.f);
}

// ---------------------------------------------------------------------------
// Kernel 4: gather (fp16 maps). One query per block; warp w does points w, w+8.
// Lane owns channels lane*8 .. lane*8+7 (one float4 = 8 halves per corner).
// ---------------------------------------------------------------------------
__global__ __launch_bounds__(256) void gather_kernel()
{
    __shared__ int4   soff[16];
    __shared__ float4 swt[16];
    __shared__ float  wacc[8][264];

    const int qidx = blockIdx.x;
    const int tid  = threadIdx.x;
    const int w    = tid >> 5;
    const int lane = tid & 31;

    if (tid < 16) {
        soff[tid] = g_soff[qidx * 16 + tid];
        swt[tid]  = g_swt [qidx * 16 + tid];
    }
    __syncthreads();

    float acc[8] = {};

#pragma unroll
    for (int t = 0; t < 2; t++) {
        const int p = w + t * 8;
        const int4   o  = soff[p];
        const float4 wt = swt[p];
        const __half* mp = (p < 8) ? g_map0 : g_map1;
        const float wx = wt.x, wy = wt.y, wz = wt.z;
        const int co = lane * 8;

        float4 r00 = __ldg((const float4*)(mp + o.x + co));
        float4 r01 = __ldg((const float4*)(mp + o.y + co));
        float4 r10 = __ldg((const float4*)(mp + o.z + co));
        float4 r11 = __ldg((const float4*)(mp + o.w + co));
        const __half2* h00 = (const __half2*)&r00;
        const __half2* h01 = (const __half2*)&r01;
        const __half2* h10 = (const __half2*)&r10;
        const __half2* h11 = (const __half2*)&r11;

#pragma unroll
        for (int j = 0; j < 4; j++) {
            float2 f00 = __half22float2(h00[j]);
            float2 f01 = __half22float2(h01[j]);
            float2 f10 = __half22float2(h10[j]);
            float2 f11 = __half22float2(h11[j]);
            float top, bot, r;
            top = f00.x + wx * (f01.x - f00.x);
            bot = f10.x + wx * (f11.x - f10.x);
            r = top + wy * (bot - top);
            acc[2 * j + 0] += wz * r;
            top = f00.y + wx * (f01.y - f00.y);
            bot = f10.y + wx * (f11.y - f10.y);
            r = top + wy * (bot - top);
            acc[2 * j + 1] += wz * r;
        }
    }

    *(float4*)&wacc[w][lane * 8]     = make_float4(acc[0], acc[1], acc[2], acc[3]);
    *(float4*)&wacc[w][lane * 8 + 4] = make_float4(acc[4], acc[5], acc[6], acc[7]);
    __syncthreads();

    float s = 0.f;
#pragma unroll
    for (int ww = 0; ww < 8; ww++)
        s += wacc[ww][tid];
    g_pre[(size_t)qidx * 256 + tid] = s;
}

// ---------------------------------------------------------------------------
// Kernel 5: C = g_pre(M,256) @ Wout(256,256) + bout.
// BM=BN=128, BK=16, 8x8 microtile (256 threads).
// ---------------------------------------------------------------------------
__global__ __launch_bounds__(256) void gemm_kernel(
    const float* __restrict__ Wt, const float* __restrict__ bias,
    float* __restrict__ C)
{
    __shared__ float As[16][128];
    __shared__ float Bs[16][128];

    const int tid = threadIdx.x;
    const int m0 = blockIdx.y * 128;
    const int n0 = blockIdx.x * 128;
    const int tx = tid & 15;       // N: tx*8
    const int ty = tid >> 4;       // M: ty*8

    float acc[8][8] = {};

    for (int k0 = 0; k0 < 256; k0 += 16) {
        // A tile: 128 rows x 16 k = 512 float4, 2 per thread, store k-major
#pragma unroll
        for (int i = 0; i < 2; i++) {
            int idx = tid + i * 256;
            int r  = idx >> 2;     // row 0..127
            int c4 = idx & 3;      // float4 col 0..3
            float4 v = *(const float4*)&g_pre[(size_t)(m0 + r) * 256 + k0 + c4 * 4];
            As[c4 * 4 + 0][r] = v.x;
            As[c4 * 4 + 1][r] = v.y;
            As[c4 * 4 + 2][r] = v.z;
            As[c4 * 4 + 3][r] = v.w;
        }
        // B tile: 16 rows x 128 n = 512 float4, 2 per thread
#pragma unroll
        for (int i = 0; i < 2; i++) {
            int idx = tid + i * 256;
            int r  = idx >> 5;     // k row 0..15
            int c4 = idx & 31;     // float4 col 0..31
            *(float4*)&Bs[r][c4 * 4] =
                *(const float4*)&Wt[(size_t)(k0 + r) * 256 + n0 + c4 * 4];
        }
        __syncthreads();

#pragma unroll
        for (int kk = 0; kk < 16; kk++) {
            float4 a0 = *(float4*)&As[kk][ty * 8];
            float4 a1 = *(float4*)&As[kk][ty * 8 + 4];
            float4 b0 = *(float4*)&Bs[kk][tx * 8];
            float4 b1 = *(float4*)&Bs[kk][tx * 8 + 4];
            float av[8] = {a0.x, a0.y, a0.z, a0.w, a1.x, a1.y, a1.z, a1.w};
            float bv[8] = {b0.x, b0.y, b0.z, b0.w, b1.x, b1.y, b1.z, b1.w};
#pragma unroll
            for (int i = 0; i < 8; i++)
#pragma unroll
                for (int j = 0; j < 8; j++)
                    acc[i][j] += av[i] * bv[j];
        }
        __syncthreads();
    }

    float4 bb0 = *(const float4*)&bias[n0 + tx * 8];
    float4 bb1 = *(const float4*)&bias[n0 + tx * 8 + 4];
    float bv[8] = {bb0.x, bb0.y, bb0.z, bb0.w, bb1.x, bb1.y, bb1.z, bb1.w};
#pragma unroll
    for (int i = 0; i < 8; i++) {
        int m = m0 + ty * 8 + i;
        float4 o0, o1;
        o0.x = acc[i][0] + bv[0];
        o0.y = acc[i][1] + bv[1];
        o0.z = acc[i][2] + bv[2];
        o0.w = acc[i][3] + bv[3];
        o1.x = acc[i][4] + bv[4];
        o1.y = acc[i][5] + bv[5];
        o1.z = acc[i][6] + bv[6];
        o1.w = acc[i][7] + bv[7];
        *(float4*)&C[(size_t)m * 256 + n0 + tx * 8]     = o0;
        *(float4*)&C[(size_t)m * 256 + n0 + tx * 8 + 4] = o1;
    }
}

// ---------------------------------------------------------------------------
extern "C" void kernel_launch(void* const* d_in, const int* in_sizes, int n_in,
                              void* d_out, int out_size)
{
    const float* q        = (const float*)d_in[0];
    const float* map0     = (const float*)d_in[1];
    const float* map1     = (const float*)d_in[2];
    const float* base_ref = (const float*)d_in[3];
    const float* Wrd      = (const float*)d_in[4];
    const float* brd      = (const float*)d_in[5];
    const float* Woff     = (const float*)d_in[6];
    const float* boff     = (const float*)d_in[7];
    const float* Wattn    = (const float*)d_in[8];
    const float* battn    = (const float*)d_in[9];
    const float* Wout     = (const float*)d_in[10];
    const float* bout     = (const float*)d_in[11];
    float* out = (float*)d_out;

    pack_weights_kernel<<<64, 256>>>(Wrd, brd, Woff, boff, Wattn, battn);

    transpose_kernel<<<dim3((H0 * W0) / 32, Dm / 64, Bn), 256>>>(map0, H0 * W0, 0);
    transpose_kernel<<<dim3((H1 * W1) / 32, Dm / 64, Bn), 256>>>(map1, H1 * W1, 1);

    proj_gemm_kernel<<<NQ / PBM, 256>>>(q);

    coord_kernel<<<NQ / 16, 256>>>(base_ref);

    gather_kernel<<<NQ, 256>>>();

    gemm_kernel<<<dim3(256 / 128, NQ / 128), 256>>>(Wout, bout, out);
}

// round 6
// speedup vs baseline: 8.1280x; 1.5768x over previous
#include <cuda_runtime.h>
#include <cuda_fp16.h>
#include <math.h>

#define Bn 4
#define Qn 8192
#define Dm 256
#define Lv 2
#define Pp 8
#define H0 128
#define W0 128
#define H1 64
#define W1 64
#define EPSV 1e-5f
#define NQ (Bn * Qn)          // 32768 total queries

// Scratch (device globals — no allocations allowed)
__device__ __half g_map0[Bn * H0 * W0 * Dm];   // (B, H*W, D) HWC fp16
__device__ __half g_map1[Bn * H1 * W1 * Dm];
__device__ __half g_pre16[NQ * Dm];            // pre-Wout accumulator (fp16)
__device__ __half g_Wout16[Dm * Dm];           // Wout in fp16
__device__ float  g_WcatP[64 * 256];           // packed transposed weights (52 used, zero pad)
__device__ float  g_bcatP[64];
__device__ float  g_dots[NQ * 64];             // projection outputs per query
__device__ int4   g_soff[NQ * 16];             // per (q,p): 4 corner element-offsets
__device__ float4 g_swt [NQ * 16];             // per (q,p): wx, wy, attn_w, 0

__device__ __forceinline__ unsigned smem_u32(const void* p) {
    return (unsigned)__cvta_generic_to_shared(p);
}

// ---------------------------------------------------------------------------
// Kernel 0a: pack projection weights transposed into 64x256 (rows 52..63 zero)
// ---------------------------------------------------------------------------
__global__ __launch_bounds__(256) void pack_weights_kernel(
    const float* __restrict__ Wrd,  const float* __restrict__ brd,
    const float* __restrict__ Woff, const float* __restrict__ boff,
    const float* __restrict__ Wattn,const float* __restrict__ battn)
{
    int j = blockIdx.x;
    int k = threadIdx.x;
    float v = 0.f, bv = 0.f;
    if (j < 4)       { v = Wrd  [k * 4  + j];      bv = brd  [j]; }
    else if (j < 36) { v = Woff [k * 32 + (j-4)];  bv = boff [j-4]; }
    else if (j < 52) { v = Wattn[k * 16 + (j-36)]; bv = battn[j-36]; }
    g_WcatP[j * 256 + k] = v;
    if (k == 0) g_bcatP[j] = bv;
}

// ---------------------------------------------------------------------------
// Kernel 0b: Wout fp32 -> fp16 (same (k,n) row-major layout)
// ---------------------------------------------------------------------------
__global__ __launch_bounds__(256) void pack_wout_kernel(const float* __restrict__ Wout)
{
    int idx = blockIdx.x * 256 + threadIdx.x;    // half2 index
    float2 v = ((const float2*)Wout)[idx];
    ((__half2*)g_Wout16)[idx] = __floats2half2_rn(v.x, v.y);
}

// ---------------------------------------------------------------------------
// Kernel 1: (B, D, HW) -> (B, HW, D) tiled transpose, fp32 -> fp16.
// ---------------------------------------------------------------------------
__global__ __launch_bounds__(256) void transpose_kernel(
    const float* __restrict__ in, int HW, int level)
{
    __shared__ float tile[64][33];
    __half* out = level ? g_map1 : g_map0;

    const int hw0 = blockIdx.x * 32;
    const int d0  = blockIdx.y * 64;
    const int b   = blockIdx.z;
    const int tid  = threadIdx.x;
    const int tx   = tid & 31;
    const int ty   = tid >> 5;

    const float* inb = in + (size_t)b * Dm * HW;
    __half* outb = out + (size_t)b * HW * Dm;

#pragma unroll
    for (int i = 0; i < 8; i++) {
        int d = d0 + ty + 8 * i;
        tile[ty + 8 * i][tx] = inb[(size_t)d * HW + hw0 + tx];
    }
    __syncthreads();

#pragma unroll
    for (int i = 0; i < 4; i++) {
        int hw = ty + 8 * i;
        __half2 v = __floats2half2_rn(tile[2 * tx][hw], tile[2 * tx + 1][hw]);
        ((__half2*)(outb + (size_t)(hw0 + hw) * Dm + d0))[tx] = v;
    }
}

// ---------------------------------------------------------------------------
// Kernel 2: projection GEMM  g_dots[NQ][64] = q(NQ x 256) @ WcatP^T + bcatP
// (unchanged from R5)
// ---------------------------------------------------------------------------
#define PBM 128
#define PBN 64
#define PBK 32

__global__ __launch_bounds__(256) void proj_gemm_kernel(const float* __restrict__ q)
{
    __shared__ float As[2][PBK][PBM];
    __shared__ float Bs[2][PBK][PBN];

    const int tid = threadIdx.x;
    const int m0 = blockIdx.x * PBM;
    const int tx = tid & 15;
    const int ty = tid >> 4;

    float acc[8][4] = {};
    float4 ra[4], rb[2];

#pragma unroll
    for (int i = 0; i < 4; i++) {
        int idx = tid + i * 256;
        int r = idx >> 3, c4 = idx & 7;
        ra[i] = *(const float4*)&q[(size_t)(m0 + r) * 256 + c4 * 4];
    }
#pragma unroll
    for (int i = 0; i < 2; i++) {
        int idx = tid + i * 256;
        int j = idx >> 3, c4 = idx & 7;
        rb[i] = *(const float4*)&g_WcatP[(size_t)j * 256 + c4 * 4];
    }
#pragma unroll
    for (int i = 0; i < 4; i++) {
        int idx = tid + i * 256;
        int r = idx >> 3, c4 = idx & 7;
        As[0][c4 * 4 + 0][r] = ra[i].x;
        As[0][c4 * 4 + 1][r] = ra[i].y;
        As[0][c4 * 4 + 2][r] = ra[i].z;
        As[0][c4 * 4 + 3][r] = ra[i].w;
    }
#pragma unroll
    for (int i = 0; i < 2; i++) {
        int idx = tid + i * 256;
        int j = idx >> 3, c4 = idx & 7;
        Bs[0][c4 * 4 + 0][j] = rb[i].x;
        Bs[0][c4 * 4 + 1][j] = rb[i].y;
        Bs[0][c4 * 4 + 2][j] = rb[i].z;
        Bs[0][c4 * 4 + 3][j] = rb[i].w;
    }
    __syncthreads();

    int buf = 0;
#pragma unroll
    for (int it = 0; it < 8; it++) {
        const int k0n = (it + 1) * PBK;
        if (it < 7) {
#pragma unroll
            for (int i = 0; i < 4; i++) {
                int idx = tid + i * 256;
                int r = idx >> 3, c4 = idx & 7;
                ra[i] = *(const float4*)&q[(size_t)(m0 + r) * 256 + k0n + c4 * 4];
            }
#pragma unroll
            for (int i = 0; i < 2; i++) {
                int idx = tid + i * 256;
                int j = idx >> 3, c4 = idx & 7;
                rb[i] = *(const float4*)&g_WcatP[(size_t)j * 256 + k0n + c4 * 4];
            }
        }

#pragma unroll
        for (int kk = 0; kk < PBK; kk++) {
            float4 a0 = *(float4*)&As[buf][kk][ty * 8];
            float4 a1 = *(float4*)&As[buf][kk][ty * 8 + 4];
            float4 bb = *(float4*)&Bs[buf][kk][tx * 4];
            float av[8] = {a0.x, a0.y, a0.z, a0.w, a1.x, a1.y, a1.z, a1.w};
            float bv[4] = {bb.x, bb.y, bb.z, bb.w};
#pragma unroll
            for (int i = 0; i < 8; i++)
#pragma unroll
                for (int j = 0; j < 4; j++)
                    acc[i][j] += av[i] * bv[j];
        }

        if (it < 7) {
            int nb = buf ^ 1;
#pragma unroll
            for (int i = 0; i < 4; i++) {
                int idx = tid + i * 256;
                int r = idx >> 3, c4 = idx & 7;
                As[nb][c4 * 4 + 0][r] = ra[i].x;
                As[nb][c4 * 4 + 1][r] = ra[i].y;
                As[nb][c4 * 4 + 2][r] = ra[i].z;
                As[nb][c4 * 4 + 3][r] = ra[i].w;
            }
#pragma unroll
            for (int i = 0; i < 2; i++) {
                int idx = tid + i * 256;
                int j = idx >> 3, c4 = idx & 7;
                Bs[nb][c4 * 4 + 0][j] = rb[i].x;
                Bs[nb][c4 * 4 + 1][j] = rb[i].y;
                Bs[nb][c4 * 4 + 2][j] = rb[i].z;
                Bs[nb][c4 * 4 + 3][j] = rb[i].w;
            }
            __syncthreads();
            buf = nb;
        }
    }

    float4 bb = *(const float4*)&g_bcatP[tx * 4];
    float bv[4] = {bb.x, bb.y, bb.z, bb.w};
#pragma unroll
    for (int i = 0; i < 8; i++) {
        int m = m0 + ty * 8 + i;
        float4 o;
        o.x = acc[i][0] + bv[0];
        o.y = acc[i][1] + bv[1];
        o.z = acc[i][2] + bv[2];
        o.w = acc[i][3] + bv[3];
        *(float4*)&g_dots[(size_t)m * 64 + tx * 4] = o;
    }
}

// ---------------------------------------------------------------------------
// Kernel 3: coords + softmax.  16 lanes per query, 16 queries per block.
// ---------------------------------------------------------------------------
__global__ __launch_bounds__(256) void coord_kernel(const float* __restrict__ base_ref)
{
    const int tid  = threadIdx.x;
    const int w    = tid >> 5;
    const int lane = tid & 31;
    const int sub  = lane >> 4;
    const int p    = lane & 15;
    const int qidx = blockIdx.x * 16 + w * 2 + sub;

    const int b = qidx >> 13;         // Qn = 8192

    const float* dots = &g_dots[(size_t)qidx * 64];

    float logit = dots[36 + p];
    float m = logit;
#pragma unroll
    for (int o = 8; o; o >>= 1)
        m = fmaxf(m, __shfl_xor_sync(0xffffffffu, m, o));
    float e = expf(logit - m);
    float esum = e;
#pragma unroll
    for (int o = 8; o; o >>= 1)
        esum += __shfl_xor_sync(0xffffffffu, esum, o);
    float wattn = e / esum;

    const int l  = p >> 3;
    const int pp = p & 7;
    const int Wl = l ? W1 : W0;
    const int Hl = l ? H1 : H0;

    float bx = base_ref[(b * Lv + l) * 2 + 0];
    float by = base_ref[(b * Lv + l) * 2 + 1];
    bx = fminf(fmaxf(bx, EPSV), 1.f - EPSV);
    by = fminf(fmaxf(by, EPSV), 1.f - EPSV);
    float lbx = logf(bx / (1.f - bx));
    float lby = logf(by / (1.f - by));
    float rx = 1.f / (1.f + expf(-(lbx + dots[l * 2 + 0])));
    float ry = 1.f / (1.f + expf(-(lby + dots[l * 2 + 1])));

    float ox = dots[4 + l * 16 + pp * 2 + 0];
    float oy = dots[4 + l * 16 + pp * 2 + 1];
    float lx = rx + ox / (float)Wl;
    float ly = ry + oy / (float)Hl;
    if (l == 1) ly = ly - floorf(ly);

    float x = lx * (float)Wl - 0.5f;
    float y = ly * (float)Hl - 0.5f;
    x = fminf(fmaxf(x, 0.f), (float)(Wl - 1));
    y = fminf(fmaxf(y, 0.f), (float)(Hl - 1));
    float x0f = floorf(x), y0f = floorf(y);
    int x0 = (int)x0f, y0 = (int)y0f;
    int x1 = min(x0 + 1, Wl - 1);
    int y1 = min(y0 + 1, Hl - 1);
    int base = b * Hl * Wl * Dm;

    int4 off;
    off.x = base + (y0 * Wl + x0) * Dm;
    off.y = base + (y0 * Wl + x1) * Dm;
    off.z = base + (y1 * Wl + x0) * Dm;
    off.w = base + (y1 * Wl + x1) * Dm;
    g_soff[qidx * 16 + p] = off;
    g_swt [qidx * 16 + p] = make_float4(x - x0f, y - y0f, wattn, 0.f);
}

// ---------------------------------------------------------------------------
// Kernel 4: gather, warp-per-query. 8 queries per block, 4096 blocks.
// Lane owns channels lane*8..lane*8+7; warp walks all 16 points in regs.
// Output written as fp16 to g_pre16.
// ---------------------------------------------------------------------------
__global__ __launch_bounds__(256) void gather_kernel()
{
    __shared__ int4   soff[8][16];
    __shared__ float4 swt [8][16];

    const int tid  = threadIdx.x;
    const int w    = tid >> 5;
    const int lane = tid & 31;
    const int q0   = blockIdx.x * 8;

    if (tid < 128) {
        int qq = tid >> 4, pp = tid & 15;
        soff[qq][pp] = g_soff[(q0 + qq) * 16 + pp];
        swt [qq][pp] = g_swt [(q0 + qq) * 16 + pp];
    }
    __syncthreads();

    const int qidx = q0 + w;
    const int co   = lane * 8;
    float acc[8] = {};

#pragma unroll
    for (int p = 0; p < 16; p++) {
        const int4   o  = soff[w][p];
        const float4 wt = swt[w][p];
        const __half* mp = (p < 8) ? g_map0 : g_map1;
        const float wx = wt.x, wy = wt.y, wz = wt.z;

        float4 r00 = __ldg((const float4*)(mp + o.x + co));
        float4 r01 = __ldg((const float4*)(mp + o.y + co));
        float4 r10 = __ldg((const float4*)(mp + o.z + co));
        float4 r11 = __ldg((const float4*)(mp + o.w + co));
        const __half2* h00 = (const __half2*)&r00;
        const __half2* h01 = (const __half2*)&r01;
        const __half2* h10 = (const __half2*)&r10;
        const __half2* h11 = (const __half2*)&r11;

#pragma unroll
        for (int j = 0; j < 4; j++) {
            float2 f00 = __half22float2(h00[j]);
            float2 f01 = __half22float2(h01[j]);
            float2 f10 = __half22float2(h10[j]);
            float2 f11 = __half22float2(h11[j]);
            float top, bot, r;
            top = f00.x + wx * (f01.x - f00.x);
            bot = f10.x + wx * (f11.x - f10.x);
            r = top + wy * (bot - top);
            acc[2 * j + 0] += wz * r;
            top = f00.y + wx * (f01.y - f00.y);
            bot = f10.y + wx * (f11.y - f10.y);
            r = top + wy * (bot - top);
            acc[2 * j + 1] += wz * r;
        }
    }

    __half2 hv[4];
#pragma unroll
    for (int j = 0; j < 4; j++)
        hv[j] = __floats2half2_rn(acc[2 * j], acc[2 * j + 1]);
    *(uint4*)&g_pre16[(size_t)qidx * 256 + co] = *(uint4*)hv;
}

// ---------------------------------------------------------------------------
// Kernel 5: C = g_pre16(M,256) @ Wout16(256,256) + bout  via HMMA m16n8k16.
// BM=BN=128, BK=32. 8 warps, warp tile 64x32.
// ---------------------------------------------------------------------------
#define APITCH 40
#define BPITCH 136

__global__ __launch_bounds__(256) void gemm_hmma_kernel(
    const float* __restrict__ bias, float* __restrict__ C)
{
    __shared__ __half As[128][APITCH];   // m x k, padded
    __shared__ __half Bs[32][BPITCH];    // k x n, padded

    const int tid  = threadIdx.x;
    const int wid  = tid >> 5;
    const int lane = tid & 31;
    const int m0 = blockIdx.y * 128;
    const int n0 = blockIdx.x * 128;
    const int wm = (wid & 1) * 64;       // warp m offset
    const int wn = (wid >> 1) * 32;      // warp n offset

    float acc[4][4][4] = {};             // [mt][nt][frag]

    const int lr = lane & 15;            // ldmatrix row-within-16
    const int lc = (lane >> 4) * 8;      // ldmatrix col offset (0/8)

    for (int k0 = 0; k0 < 256; k0 += 32) {
        // load A tile: 128 x 32 halves
#pragma unroll
        for (int i = 0; i < 2; i++) {
            int idx = tid + i * 256;
            int r = idx >> 2, c8 = idx & 3;
            uint4 v = *(const uint4*)&g_pre16[(size_t)(m0 + r) * 256 + k0 + c8 * 8];
            *(uint4*)&As[r][c8 * 8] = v;
        }
        // load B tile: 32 x 128 halves
#pragma unroll
        for (int i = 0; i < 2; i++) {
            int idx = tid + i * 256;
            int r = idx >> 4, c8 = idx & 15;
            uint4 v = *(const uint4*)&g_Wout16[(size_t)(k0 + r) * 256 + n0 + c8 * 8];
            *(uint4*)&Bs[r][c8 * 8] = v;
        }
        __syncthreads();

#pragma unroll
        for (int kk = 0; kk < 32; kk += 16) {
            unsigned a[4][4];
#pragma unroll
            for (int mt = 0; mt < 4; mt++) {
                unsigned addr = smem_u32(&As[wm + mt * 16 + lr][kk + lc]);
                asm volatile(
                    "ldmatrix.sync.aligned.m8n8.x4.shared.b16 {%0,%1,%2,%3}, [%4];"
                    : "=r"(a[mt][0]), "=r"(a[mt][1]), "=r"(a[mt][2]), "=r"(a[mt][3])
                    : "r"(addr));
            }
            unsigned b[2][4];
#pragma unroll
            for (int ng = 0; ng < 2; ng++) {
                unsigned addr = smem_u32(&Bs[kk + lr][wn + ng * 16 + lc]);
                asm volatile(
                    "ldmatrix.sync.aligned.m8n8.x4.trans.shared.b16 {%0,%1,%2,%3}, [%4];"
                    : "=r"(b[ng][0]), "=r"(b[ng][1]), "=r"(b[ng][2]), "=r"(b[ng][3])
                    : "r"(addr));
            }
#pragma unroll
            for (int mt = 0; mt < 4; mt++) {
#pragma unroll
                for (int nt = 0; nt < 4; nt++) {
                    unsigned b0 = b[nt >> 1][(nt & 1) * 2 + 0];
                    unsigned b1 = b[nt >> 1][(nt & 1) * 2 + 1];
                    asm volatile(
                        "mma.sync.aligned.m16n8k16.row.col.f32.f16.f16.f32 "
                        "{%0,%1,%2,%3}, {%4,%5,%6,%7}, {%8,%9}, {%0,%1,%2,%3};"
                        : "+f"(acc[mt][nt][0]), "+f"(acc[mt][nt][1]),
                          "+f"(acc[mt][nt][2]), "+f"(acc[mt][nt][3])
                        : "r"(a[mt][0]), "r"(a[mt][1]), "r"(a[mt][2]), "r"(a[mt][3]),
                          "r"(b0), "r"(b1));
                }
            }
        }
        __syncthreads();
    }

    // epilogue: D[row][col] + bias
    const int gr = lane >> 2;            // 0..7
    const int gc = (lane & 3) * 2;       // 0,2,4,6
#pragma unroll
    for (int mt = 0; mt < 4; mt++) {
#pragma unroll
        for (int nt = 0; nt < 4; nt++) {
            int col = n0 + wn + nt * 8 + gc;
            float2 bv = *(const float2*)&bias[col];
            int row0 = m0 + wm + mt * 16 + gr;
            float2 o0 = make_float2(acc[mt][nt][0] + bv.x, acc[mt][nt][1] + bv.y);
            float2 o1 = make_float2(acc[mt][nt][2] + bv.x, acc[mt][nt][3] + bv.y);
            *(float2*)&C[(size_t)row0 * 256 + col]       = o0;
            *(float2*)&C[(size_t)(row0 + 8) * 256 + col] = o1;
        }
    }
}

// ---------------------------------------------------------------------------
extern "C" void kernel_launch(void* const* d_in, const int* in_sizes, int n_in,
                              void* d_out, int out_size)
{
    const float* q        = (const float*)d_in[0];
    const float* map0     = (const float*)d_in[1];
    const float* map1     = (const float*)d_in[2];
    const float* base_ref = (const float*)d_in[3];
    const float* Wrd      = (const float*)d_in[4];
    const float* brd      = (const float*)d_in[5];
    const float* Woff     = (const float*)d_in[6];
    const float* boff     = (const float*)d_in[7];
    const float* Wattn    = (const float*)d_in[8];
    const float* battn    = (const float*)d_in[9];
    const float* Wout     = (const float*)d_in[10];
    const float* bout     = (const float*)d_in[11];
    float* out = (float*)d_out;

    pack_weights_kernel<<<64, 256>>>(Wrd, brd, Woff, boff, Wattn, battn);
    pack_wout_kernel<<<128, 256>>>(Wout);

    transpose_kernel<<<dim3((H0 * W0) / 32, Dm / 64, Bn), 256>>>(map0, H0 * W0, 0);
    transpose_kernel<<<dim3((H1 * W1) / 32, Dm / 64, Bn), 256>>>(map1, H1 * W1, 1);

    proj_gemm_kernel<<<NQ / PBM, 256>>>(q);

    coord_kernel<<<NQ / 16, 256>>>(base_ref);

    gather_kernel<<<NQ / 8, 256>>>();

    gemm_hmma_kernel<<<dim3(2, NQ / 128), 256>>>(bout, out);
}

// round 7
// speedup vs baseline: 9.1890x; 1.1305x over previous
#include <cuda_runtime.h>
#include <cuda_fp16.h>
#include <math.h>

#define Bn 4
#define Qn 8192
#define Dm 256
#define Lv 2
#define Pp 8
#define H0 128
#define W0 128
#define H1 64
#define W1 64
#define EPSV 1e-5f
#define NQ (Bn * Qn)          // 32768 total queries

// Scratch (device globals — no allocations allowed)
__device__ __half g_map0[Bn * H0 * W0 * Dm];   // (B, H*W, D) HWC fp16
__device__ __half g_map1[Bn * H1 * W1 * Dm];
__device__ __half g_pre16[NQ * Dm];            // pre-Wout accumulator (fp16)
__device__ __half g_Wout16[Dm * Dm];           // Wout in fp16
__device__ float  g_WcatKM[256 * 64];          // packed weights, k-major [k][j]
__device__ float  g_bcatP[64];
__device__ float  g_dots[NQ * 64];             // projection outputs per query
__device__ int4   g_soff[NQ * 16];             // per (q,p): 4 corner element-offsets
__device__ float4 g_swt [NQ * 16];             // per (q,p): wx, wy, attn_w, 0

__device__ __forceinline__ unsigned smem_u32(const void* p) {
    return (unsigned)__cvta_generic_to_shared(p);
}
__device__ __forceinline__ void cpa16(unsigned d, const void* s) {
    asm volatile("cp.async.cg.shared.global [%0], [%1], 16;" :: "r"(d), "l"(s));
}

// ---------------------------------------------------------------------------
// Kernel 0a: pack projection weights k-major into g_WcatKM[k][j] (j 52..63 = 0)
// ---------------------------------------------------------------------------
__global__ __launch_bounds__(256) void pack_weights_kernel(
    const float* __restrict__ Wrd,  const float* __restrict__ brd,
    const float* __restrict__ Woff, const float* __restrict__ boff,
    const float* __restrict__ Wattn,const float* __restrict__ battn)
{
    int j = blockIdx.x;
    int k = threadIdx.x;
    float v = 0.f, bv = 0.f;
    if (j < 4)       { v = Wrd  [k * 4  + j];      bv = brd  [j]; }
    else if (j < 36) { v = Woff [k * 32 + (j-4)];  bv = boff [j-4]; }
    else if (j < 52) { v = Wattn[k * 16 + (j-36)]; bv = battn[j-36]; }
    g_WcatKM[k * 64 + j] = v;
    if (k == 0) g_bcatP[j] = bv;
}

// ---------------------------------------------------------------------------
// Kernel 0b: Wout fp32 -> fp16 (same (k,n) row-major layout)
// ---------------------------------------------------------------------------
__global__ __launch_bounds__(256) void pack_wout_kernel(const float* __restrict__ Wout)
{
    int idx = blockIdx.x * 256 + threadIdx.x;    // half2 index
    float2 v = ((const float2*)Wout)[idx];
    ((__half2*)g_Wout16)[idx] = __floats2half2_rn(v.x, v.y);
}

// ---------------------------------------------------------------------------
// Kernel 1: (B, D, HW) -> (B, HW, D) tiled transpose, fp32 -> fp16.
// ---------------------------------------------------------------------------
__global__ __launch_bounds__(256) void transpose_kernel(
    const float* __restrict__ in, int HW, int level)
{
    __shared__ float tile[64][33];
    __half* out = level ? g_map1 : g_map0;

    const int hw0 = blockIdx.x * 32;
    const int d0  = blockIdx.y * 64;
    const int b   = blockIdx.z;
    const int tid  = threadIdx.x;
    const int tx   = tid & 31;
    const int ty   = tid >> 5;

    const float* inb = in + (size_t)b * Dm * HW;
    __half* outb = out + (size_t)b * HW * Dm;

#pragma unroll
    for (int i = 0; i < 8; i++) {
        int d = d0 + ty + 8 * i;
        tile[ty + 8 * i][tx] = inb[(size_t)d * HW + hw0 + tx];
    }
    __syncthreads();

#pragma unroll
    for (int i = 0; i < 4; i++) {
        int hw = ty + 8 * i;
        __half2 v = __floats2half2_rn(tile[2 * tx][hw], tile[2 * tx + 1][hw]);
        ((__half2*)(outb + (size_t)(hw0 + hw) * Dm + d0))[tx] = v;
    }
}

// ---------------------------------------------------------------------------
// Kernel 2: projection GEMM  g_dots[NQ][64] = q(NQ x 256) @ Wcat + bcat
// BM=64, BN=64, BK=32, 2-stage cp.async pipeline, 4x4 microtile.
// ---------------------------------------------------------------------------
#define APITCH 36    // 144B rows, 16B aligned
#define BKPITCH 68   // 272B rows, 16B aligned

__global__ __launch_bounds__(256) void proj_gemm_kernel(const float* __restrict__ q)
{
    __shared__ __align__(16) float As[2][64 * APITCH];   // [m][k] row-major
    __shared__ __align__(16) float Bs[2][32 * BKPITCH];  // [k][n] k-major

    const int tid = threadIdx.x;
    const int m0 = blockIdx.x * 64;
    const int tx = tid & 15;       // n: tx*4
    const int ty = tid >> 4;       // m: ty*4

    const int ar = tid >> 3;            // A row (0..63 over 2 iters)
    const int ac = (tid & 7) * 4;       // A col (float4)
    const int br = tid >> 4;            // B k-row (0..31 over 2 iters)
    const int bc = (tid & 15) * 4;      // B n-col (float4)

    // ---- prologue: stage 0 ----
    {
        const int k0 = 0;
        cpa16(smem_u32(&As[0][ar * APITCH + ac]),          &q[(size_t)(m0 + ar) * 256 + k0 + ac]);
        cpa16(smem_u32(&As[0][(ar + 32) * APITCH + ac]),   &q[(size_t)(m0 + ar + 32) * 256 + k0 + ac]);
        cpa16(smem_u32(&Bs[0][br * BKPITCH + bc]),         &g_WcatKM[(k0 + br) * 64 + bc]);
        cpa16(smem_u32(&Bs[0][(br + 16) * BKPITCH + bc]),  &g_WcatKM[(k0 + br + 16) * 64 + bc]);
        asm volatile("cp.async.commit_group;");
    }

    float acc[4][4] = {};

#pragma unroll
    for (int it = 0; it < 8; it++) {
        if (it + 1 < 8) {
            const int k0 = (it + 1) * 32;
            const int s = (it + 1) & 1;
            cpa16(smem_u32(&As[s][ar * APITCH + ac]),          &q[(size_t)(m0 + ar) * 256 + k0 + ac]);
            cpa16(smem_u32(&As[s][(ar + 32) * APITCH + ac]),   &q[(size_t)(m0 + ar + 32) * 256 + k0 + ac]);
            cpa16(smem_u32(&Bs[s][br * BKPITCH + bc]),         &g_WcatKM[(k0 + br) * 64 + bc]);
            cpa16(smem_u32(&Bs[s][(br + 16) * BKPITCH + bc]),  &g_WcatKM[(k0 + br + 16) * 64 + bc]);
            asm volatile("cp.async.commit_group;");
            asm volatile("cp.async.wait_group 1;");
        } else {
            asm volatile("cp.async.wait_group 0;");
        }
        __syncthreads();

        const int s = it & 1;
#pragma unroll
        for (int kk = 0; kk < 32; kk++) {
            float a0 = As[s][(ty * 4 + 0) * APITCH + kk];
            float a1 = As[s][(ty * 4 + 1) * APITCH + kk];
            float a2 = As[s][(ty * 4 + 2) * APITCH + kk];
            float a3 = As[s][(ty * 4 + 3) * APITCH + kk];
            float4 b = *(const float4*)&Bs[s][kk * BKPITCH + tx * 4];
            float av[4] = {a0, a1, a2, a3};
            float bv[4] = {b.x, b.y, b.z, b.w};
#pragma unroll
            for (int i = 0; i < 4; i++)
#pragma unroll
                for (int j = 0; j < 4; j++)
                    acc[i][j] += av[i] * bv[j];
        }
        __syncthreads();
    }

    float4 bb = *(const float4*)&g_bcatP[tx * 4];
    float bv[4] = {bb.x, bb.y, bb.z, bb.w};
#pragma unroll
    for (int i = 0; i < 4; i++) {
        int m = m0 + ty * 4 + i;
        float4 o;
        o.x = acc[i][0] + bv[0];
        o.y = acc[i][1] + bv[1];
        o.z = acc[i][2] + bv[2];
        o.w = acc[i][3] + bv[3];
        *(float4*)&g_dots[(size_t)m * 64 + tx * 4] = o;
    }
}

// ---------------------------------------------------------------------------
// Kernel 3: coords + softmax.  16 lanes per query, 16 queries per block.
// ---------------------------------------------------------------------------
__global__ __launch_bounds__(256) void coord_kernel(const float* __restrict__ base_ref)
{
    const int tid  = threadIdx.x;
    const int w    = tid >> 5;
    const int lane = tid & 31;
    const int sub  = lane >> 4;
    const int p    = lane & 15;
    const int qidx = blockIdx.x * 16 + w * 2 + sub;

    const int b = qidx >> 13;         // Qn = 8192

    const float* dots = &g_dots[(size_t)qidx * 64];

    float logit = dots[36 + p];
    float m = logit;
#pragma unroll
    for (int o = 8; o; o >>= 1)
        m = fmaxf(m, __shfl_xor_sync(0xffffffffu, m, o));
    float e = expf(logit - m);
    float esum = e;
#pragma unroll
    for (int o = 8; o; o >>= 1)
        esum += __shfl_xor_sync(0xffffffffu, esum, o);
    float wattn = e / esum;

    const int l  = p >> 3;
    const int pp = p & 7;
    const int Wl = l ? W1 : W0;
    const int Hl = l ? H1 : H0;

    float bx = base_ref[(b * Lv + l) * 2 + 0];
    float by = base_ref[(b * Lv + l) * 2 + 1];
    bx = fminf(fmaxf(bx, EPSV), 1.f - EPSV);
    by = fminf(fmaxf(by, EPSV), 1.f - EPSV);
    float lbx = logf(bx / (1.f - bx));
    float lby = logf(by / (1.f - by));
    float rx = 1.f / (1.f + expf(-(lbx + dots[l * 2 + 0])));
    float ry = 1.f / (1.f + expf(-(lby + dots[l * 2 + 1])));

    float ox = dots[4 + l * 16 + pp * 2 + 0];
    float oy = dots[4 + l * 16 + pp * 2 + 1];
    float lx = rx + ox / (float)Wl;
    float ly = ry + oy / (float)Hl;
    if (l == 1) ly = ly - floorf(ly);

    float x = lx * (float)Wl - 0.5f;
    float y = ly * (float)Hl - 0.5f;
    x = fminf(fmaxf(x, 0.f), (float)(Wl - 1));
    y = fminf(fmaxf(y, 0.f), (float)(Hl - 1));
    float x0f = floorf(x), y0f = floorf(y);
    int x0 = (int)x0f, y0 = (int)y0f;
    int x1 = min(x0 + 1, Wl - 1);
    int y1 = min(y0 + 1, Hl - 1);
    int base = b * Hl * Wl * Dm;

    int4 off;
    off.x = base + (y0 * Wl + x0) * Dm;
    off.y = base + (y0 * Wl + x1) * Dm;
    off.z = base + (y1 * Wl + x0) * Dm;
    off.w = base + (y1 * Wl + x1) * Dm;
    g_soff[qidx * 16 + p] = off;
    g_swt [qidx * 16 + p] = make_float4(x - x0f, y - y0f, wattn, 0.f);
}

// ---------------------------------------------------------------------------
// Kernel 4: gather, warp-per-query. 8 queries per block, 4096 blocks.
// ---------------------------------------------------------------------------
__global__ __launch_bounds__(256) void gather_kernel()
{
    __shared__ int4   soff[8][16];
    __shared__ float4 swt [8][16];

    const int tid  = threadIdx.x;
    const int w    = tid >> 5;
    const int lane = tid & 31;
    const int q0   = blockIdx.x * 8;

    if (tid < 128) {
        int qq = tid >> 4, pp = tid & 15;
        soff[qq][pp] = g_soff[(q0 + qq) * 16 + pp];
        swt [qq][pp] = g_swt [(q0 + qq) * 16 + pp];
    }
    __syncthreads();

    const int qidx = q0 + w;
    const int co   = lane * 8;
    float acc[8] = {};

#pragma unroll
    for (int p = 0; p < 16; p++) {
        const int4   o  = soff[w][p];
        const float4 wt = swt[w][p];
        const __half* mp = (p < 8) ? g_map0 : g_map1;
        const float wx = wt.x, wy = wt.y, wz = wt.z;

        float4 r00 = __ldg((const float4*)(mp + o.x + co));
        float4 r01 = __ldg((const float4*)(mp + o.y + co));
        float4 r10 = __ldg((const float4*)(mp + o.z + co));
        float4 r11 = __ldg((const float4*)(mp + o.w + co));
        const __half2* h00 = (const __half2*)&r00;
        const __half2* h01 = (const __half2*)&r01;
        const __half2* h10 = (const __half2*)&r10;
        const __half2* h11 = (const __half2*)&r11;

#pragma unroll
        for (int j = 0; j < 4; j++) {
            float2 f00 = __half22float2(h00[j]);
            float2 f01 = __half22float2(h01[j]);
            float2 f10 = __half22float2(h10[j]);
            float2 f11 = __half22float2(h11[j]);
            float top, bot, r;
            top = f00.x + wx * (f01.x - f00.x);
            bot = f10.x + wx * (f11.x - f10.x);
            r = top + wy * (bot - top);
            acc[2 * j + 0] += wz * r;
            top = f00.y + wx * (f01.y - f00.y);
            bot = f10.y + wx * (f11.y - f10.y);
            r = top + wy * (bot - top);
            acc[2 * j + 1] += wz * r;
        }
    }

    __half2 hv[4];
#pragma unroll
    for (int j = 0; j < 4; j++)
        hv[j] = __floats2half2_rn(acc[2 * j], acc[2 * j + 1]);
    *(uint4*)&g_pre16[(size_t)qidx * 256 + co] = *(uint4*)hv;
}

// ---------------------------------------------------------------------------
// Kernel 5: C = g_pre16(M,256) @ Wout16(256,256) + bout  via HMMA m16n8k16.
// ---------------------------------------------------------------------------
#define HAPITCH 40
#define HBPITCH 136

__global__ __launch_bounds__(256) void gemm_hmma_kernel(
    const float* __restrict__ bias, float* __restrict__ C)
{
    __shared__ __half As[128][HAPITCH];
    __shared__ __half Bs[32][HBPITCH];

    const int tid  = threadIdx.x;
    const int wid  = tid >> 5;
    const int lane = tid & 31;
    const int m0 = blockIdx.y * 128;
    const int n0 = blockIdx.x * 128;
    const int wm = (wid & 1) * 64;
    const int wn = (wid >> 1) * 32;

    float acc[4][4][4] = {};

    const int lr = lane & 15;
    const int lc = (lane >> 4) * 8;

    for (int k0 = 0; k0 < 256; k0 += 32) {
#pragma unroll
        for (int i = 0; i < 2; i++) {
            int idx = tid + i * 256;
            int r = idx >> 2, c8 = idx & 3;
            uint4 v = *(const uint4*)&g_pre16[(size_t)(m0 + r) * 256 + k0 + c8 * 8];
            *(uint4*)&As[r][c8 * 8] = v;
        }
#pragma unroll
        for (int i = 0; i < 2; i++) {
            int idx = tid + i * 256;
            int r = idx >> 4, c8 = idx & 15;
            uint4 v = *(const uint4*)&g_Wout16[(size_t)(k0 + r) * 256 + n0 + c8 * 8];
            *(uint4*)&Bs[r][c8 * 8] = v;
        }
        __syncthreads();

#pragma unroll
        for (int kk = 0; kk < 32; kk += 16) {
            unsigned a[4][4];
#pragma unroll
            for (int mt = 0; mt < 4; mt++) {
                unsigned addr = smem_u32(&As[wm + mt * 16 + lr][kk + lc]);
                asm volatile(
                    "ldmatrix.sync.aligned.m8n8.x4.shared.b16 {%0,%1,%2,%3}, [%4];"
                    : "=r"(a[mt][0]), "=r"(a[mt][1]), "=r"(a[mt][2]), "=r"(a[mt][3])
                    : "r"(addr));
            }
            unsigned b[2][4];
#pragma unroll
            for (int ng = 0; ng < 2; ng++) {
                unsigned addr = smem_u32(&Bs[kk + lr][wn + ng * 16 + lc]);
                asm volatile(
                    "ldmatrix.sync.aligned.m8n8.x4.trans.shared.b16 {%0,%1,%2,%3}, [%4];"
                    : "=r"(b[ng][0]), "=r"(b[ng][1]), "=r"(b[ng][2]), "=r"(b[ng][3])
                    : "r"(addr));
            }
#pragma unroll
            for (int mt = 0; mt < 4; mt++) {
#pragma unroll
                for (int nt = 0; nt < 4; nt++) {
                    unsigned b0 = b[nt >> 1][(nt & 1) * 2 + 0];
                    unsigned b1 = b[nt >> 1][(nt & 1) * 2 + 1];
                    asm volatile(
                        "mma.sync.aligned.m16n8k16.row.col.f32.f16.f16.f32 "
                        "{%0,%1,%2,%3}, {%4,%5,%6,%7}, {%8,%9}, {%0,%1,%2,%3};"
                        : "+f"(acc[mt][nt][0]), "+f"(acc[mt][nt][1]),
                          "+f"(acc[mt][nt][2]), "+f"(acc[mt][nt][3])
                        : "r"(a[mt][0]), "r"(a[mt][1]), "r"(a[mt][2]), "r"(a[mt][3]),
                          "r"(b0), "r"(b1));
                }
            }
        }
        __syncthreads();
    }

    const int gr = lane >> 2;
    const int gc = (lane & 3) * 2;
#pragma unroll
    for (int mt = 0; mt < 4; mt++) {
#pragma unroll
        for (int nt = 0; nt < 4; nt++) {
            int col = n0 + wn + nt * 8 + gc;
            float2 bv = *(const float2*)&bias[col];
            int row0 = m0 + wm + mt * 16 + gr;
            float2 o0 = make_float2(acc[mt][nt][0] + bv.x, acc[mt][nt][1] + bv.y);
            float2 o1 = make_float2(acc[mt][nt][2] + bv.x, acc[mt][nt][3] + bv.y);
            *(float2*)&C[(size_t)row0 * 256 + col]       = o0;
            *(float2*)&C[(size_t)(row0 + 8) * 256 + col] = o1;
        }
    }
}

// ---------------------------------------------------------------------------
extern "C" void kernel_launch(void* const* d_in, const int* in_sizes, int n_in,
                              void* d_out, int out_size)
{
    const float* q        = (const float*)d_in[0];
    const float* map0     = (const float*)d_in[1];
    const float* map1     = (const float*)d_in[2];
    const float* base_ref = (const float*)d_in[3];
    const float* Wrd      = (const float*)d_in[4];
    const float* brd      = (const float*)d_in[5];
    const float* Woff     = (const float*)d_in[6];
    const float* boff     = (const float*)d_in[7];
    const float* Wattn    = (const float*)d_in[8];
    const float* battn    = (const float*)d_in[9];
    const float* Wout     = (const float*)d_in[10];
    const float* bout     = (const float*)d_in[11];
    float* out = (float*)d_out;

    pack_weights_kernel<<<64, 256>>>(Wrd, brd, Woff, boff, Wattn, battn);
    pack_wout_kernel<<<128, 256>>>(Wout);

    transpose_kernel<<<dim3((H0 * W0) / 32, Dm / 64, Bn), 256>>>(map0, H0 * W0, 0);
    transpose_kernel<<<dim3((H1 * W1) / 32, Dm / 64, Bn), 256>>>(map1, H1 * W1, 1);

    proj_gemm_kernel<<<NQ / 64, 256>>>(q);

    coord_kernel<<<NQ / 16, 256>>>(base_ref);

    gather_kernel<<<NQ / 8, 256>>>();

    gemm_hmma_kernel<<<dim3(2, NQ / 128), 256>>>(bout, out);
}

// round 8
// speedup vs baseline: 10.0678x; 1.0956x over previous
#include <cuda_runtime.h>
#include <cuda_fp16.h>
#include <math.h>

#define Bn 4
#define Qn 8192
#define Dm 256
#define Lv 2
#define Pp 8
#define H0 128
#define W0 128
#define H1 64
#define W1 64
#define EPSV 1e-5f
#define NQ (Bn * Qn)          // 32768 total queries

// Scratch (device globals — no allocations allowed)
__device__ __half g_map0[Bn * H0 * W0 * Dm];   // (B, H*W, D) HWC fp16
__device__ __half g_map1[Bn * H1 * W1 * Dm];
__device__ __half g_pre16[NQ * Dm];            // pre-Wout accumulator (fp16)
__device__ __half g_Wout16[Dm * Dm];           // Wout in fp16
__device__ float  g_WcatKM[256 * 64];          // packed weights, k-major [k][j]
__device__ float  g_bcatP[64];
__device__ float  g_dots[NQ * 64];             // projection outputs per query
__device__ int4   g_soff[NQ * 16];             // per (q,p): 4 corner element-offsets
__device__ float4 g_cw  [NQ * 16];             // per (q,p): combined corner weights w00,w01,w10,w11

__device__ __forceinline__ unsigned smem_u32(const void* p) {
    return (unsigned)__cvta_generic_to_shared(p);
}
__device__ __forceinline__ void cpa16(unsigned d, const void* s) {
    asm volatile("cp.async.cg.shared.global [%0], [%1], 16;" :: "r"(d), "l"(s));
}

// ---------------------------------------------------------------------------
// Kernel 0a: pack projection weights k-major into g_WcatKM[k][j] (j 52..63 = 0)
// ---------------------------------------------------------------------------
__global__ __launch_bounds__(256) void pack_weights_kernel(
    const float* __restrict__ Wrd,  const float* __restrict__ brd,
    const float* __restrict__ Woff, const float* __restrict__ boff,
    const float* __restrict__ Wattn,const float* __restrict__ battn)
{
    int j = blockIdx.x;
    int k = threadIdx.x;
    float v = 0.f, bv = 0.f;
    if (j < 4)       { v = Wrd  [k * 4  + j];      bv = brd  [j]; }
    else if (j < 36) { v = Woff [k * 32 + (j-4)];  bv = boff [j-4]; }
    else if (j < 52) { v = Wattn[k * 16 + (j-36)]; bv = battn[j-36]; }
    g_WcatKM[k * 64 + j] = v;
    if (k == 0) g_bcatP[j] = bv;
}

// ---------------------------------------------------------------------------
// Kernel 0b: Wout fp32 -> fp16 (same (k,n) row-major layout)
// ---------------------------------------------------------------------------
__global__ __launch_bounds__(256) void pack_wout_kernel(const float* __restrict__ Wout)
{
    int idx = blockIdx.x * 256 + threadIdx.x;    // half2 index
    float2 v = ((const float2*)Wout)[idx];
    ((__half2*)g_Wout16)[idx] = __floats2half2_rn(v.x, v.y);
}

// ---------------------------------------------------------------------------
// Kernel 1: (B, D, HW) -> (B, HW, D) tiled transpose, fp32 -> fp16.
// ---------------------------------------------------------------------------
__global__ __launch_bounds__(256) void transpose_kernel(
    const float* __restrict__ in, int HW, int level)
{
    __shared__ float tile[64][33];
    __half* out = level ? g_map1 : g_map0;

    const int hw0 = blockIdx.x * 32;
    const int d0  = blockIdx.y * 64;
    const int b   = blockIdx.z;
    const int tid  = threadIdx.x;
    const int tx   = tid & 31;
    const int ty   = tid >> 5;

    const float* inb = in + (size_t)b * Dm * HW;
    __half* outb = out + (size_t)b * HW * Dm;

#pragma unroll
    for (int i = 0; i < 8; i++) {
        int d = d0 + ty + 8 * i;
        tile[ty + 8 * i][tx] = inb[(size_t)d * HW + hw0 + tx];
    }
    __syncthreads();

#pragma unroll
    for (int i = 0; i < 4; i++) {
        int hw = ty + 8 * i;
        __half2 v = __floats2half2_rn(tile[2 * tx][hw], tile[2 * tx + 1][hw]);
        ((__half2*)(outb + (size_t)(hw0 + hw) * Dm + d0))[tx] = v;
    }
}

// ---------------------------------------------------------------------------
// Kernel 2: projection GEMM  g_dots[NQ][64] = q(NQ x 256) @ Wcat + bcat
// BM=64, BN=64, BK=32, 2-stage cp.async pipeline, 4x4 microtile.
// Inner loop reads A as float4-along-k (fewer LDS instructions).
// ---------------------------------------------------------------------------
#define APITCH 36    // 144B rows, 16B aligned
#define BKPITCH 68   // 272B rows, 16B aligned

__global__ __launch_bounds__(256) void proj_gemm_kernel(const float* __restrict__ q)
{
    __shared__ __align__(16) float As[2][64 * APITCH];   // [m][k] row-major
    __shared__ __align__(16) float Bs[2][32 * BKPITCH];  // [k][n] k-major

    const int tid = threadIdx.x;
    const int m0 = blockIdx.x * 64;
    const int tx = tid & 15;       // n: tx*4
    const int ty = tid >> 4;       // m: ty*4

    const int ar = tid >> 3;            // A row (0..63 over 2 iters)
    const int ac = (tid & 7) * 4;       // A col (float4)
    const int br = tid >> 4;            // B k-row (0..31 over 2 iters)
    const int bc = (tid & 15) * 4;      // B n-col (float4)

    // ---- prologue: stage 0 ----
    {
        const int k0 = 0;
        cpa16(smem_u32(&As[0][ar * APITCH + ac]),          &q[(size_t)(m0 + ar) * 256 + k0 + ac]);
        cpa16(smem_u32(&As[0][(ar + 32) * APITCH + ac]),   &q[(size_t)(m0 + ar + 32) * 256 + k0 + ac]);
        cpa16(smem_u32(&Bs[0][br * BKPITCH + bc]),         &g_WcatKM[(k0 + br) * 64 + bc]);
        cpa16(smem_u32(&Bs[0][(br + 16) * BKPITCH + bc]),  &g_WcatKM[(k0 + br + 16) * 64 + bc]);
        asm volatile("cp.async.commit_group;");
    }

    float acc[4][4] = {};

#pragma unroll
    for (int it = 0; it < 8; it++) {
        if (it + 1 < 8) {
            const int k0 = (it + 1) * 32;
            const int s = (it + 1) & 1;
            cpa16(smem_u32(&As[s][ar * APITCH + ac]),          &q[(size_t)(m0 + ar) * 256 + k0 + ac]);
            cpa16(smem_u32(&As[s][(ar + 32) * APITCH + ac]),   &q[(size_t)(m0 + ar + 32) * 256 + k0 + ac]);
            cpa16(smem_u32(&Bs[s][br * BKPITCH + bc]),         &g_WcatKM[(k0 + br) * 64 + bc]);
            cpa16(smem_u32(&Bs[s][(br + 16) * BKPITCH + bc]),  &g_WcatKM[(k0 + br + 16) * 64 + bc]);
            asm volatile("cp.async.commit_group;");
            asm volatile("cp.async.wait_group 1;");
        } else {
            asm volatile("cp.async.wait_group 0;");
        }
        __syncthreads();

        const int s = it & 1;
#pragma unroll
        for (int kk = 0; kk < 32; kk += 4) {
            float4 a[4], b[4];
#pragma unroll
            for (int i = 0; i < 4; i++)
                a[i] = *(const float4*)&As[s][(ty * 4 + i) * APITCH + kk];
#pragma unroll
            for (int j = 0; j < 4; j++)
                b[j] = *(const float4*)&Bs[s][(kk + j) * BKPITCH + tx * 4];
#pragma unroll
            for (int kj = 0; kj < 4; kj++) {
                float av[4];
#pragma unroll
                for (int i = 0; i < 4; i++)
                    av[i] = ((const float*)&a[i])[kj];
                const float* bv = (const float*)&b[kj];
#pragma unroll
                for (int i = 0; i < 4; i++)
#pragma unroll
                    for (int j = 0; j < 4; j++)
                        acc[i][j] += av[i] * bv[j];
            }
        }
        __syncthreads();
    }

    float4 bb = *(const float4*)&g_bcatP[tx * 4];
    float bv[4] = {bb.x, bb.y, bb.z, bb.w};
#pragma unroll
    for (int i = 0; i < 4; i++) {
        int m = m0 + ty * 4 + i;
        float4 o;
        o.x = acc[i][0] + bv[0];
        o.y = acc[i][1] + bv[1];
        o.z = acc[i][2] + bv[2];
        o.w = acc[i][3] + bv[3];
        *(float4*)&g_dots[(size_t)m * 64 + tx * 4] = o;
    }
}

// ---------------------------------------------------------------------------
// Kernel 3: coords + softmax + combined corner weights.
// ---------------------------------------------------------------------------
__global__ __launch_bounds__(256) void coord_kernel(const float* __restrict__ base_ref)
{
    const int tid  = threadIdx.x;
    const int w    = tid >> 5;
    const int lane = tid & 31;
    const int sub  = lane >> 4;
    const int p    = lane & 15;
    const int qidx = blockIdx.x * 16 + w * 2 + sub;

    const int b = qidx >> 13;         // Qn = 8192

    const float* dots = &g_dots[(size_t)qidx * 64];

    float logit = dots[36 + p];
    float m = logit;
#pragma unroll
    for (int o = 8; o; o >>= 1)
        m = fmaxf(m, __shfl_xor_sync(0xffffffffu, m, o));
    float e = expf(logit - m);
    float esum = e;
#pragma unroll
    for (int o = 8; o; o >>= 1)
        esum += __shfl_xor_sync(0xffffffffu, esum, o);
    float wattn = e / esum;

    const int l  = p >> 3;
    const int pp = p & 7;
    const int Wl = l ? W1 : W0;
    const int Hl = l ? H1 : H0;

    float bx = base_ref[(b * Lv + l) * 2 + 0];
    float by = base_ref[(b * Lv + l) * 2 + 1];
    bx = fminf(fmaxf(bx, EPSV), 1.f - EPSV);
    by = fminf(fmaxf(by, EPSV), 1.f - EPSV);
    float lbx = logf(bx / (1.f - bx));
    float lby = logf(by / (1.f - by));
    float rx = 1.f / (1.f + expf(-(lbx + dots[l * 2 + 0])));
    float ry = 1.f / (1.f + expf(-(lby + dots[l * 2 + 1])));

    float ox = dots[4 + l * 16 + pp * 2 + 0];
    float oy = dots[4 + l * 16 + pp * 2 + 1];
    float lx = rx + ox / (float)Wl;
    float ly = ry + oy / (float)Hl;
    if (l == 1) ly = ly - floorf(ly);

    float x = lx * (float)Wl - 0.5f;
    float y = ly * (float)Hl - 0.5f;
    x = fminf(fmaxf(x, 0.f), (float)(Wl - 1));
    y = fminf(fmaxf(y, 0.f), (float)(Hl - 1));
    float x0f = floorf(x), y0f = floorf(y);
    float wx = x - x0f, wy = y - y0f;
    int x0 = (int)x0f, y0 = (int)y0f;
    int x1 = min(x0 + 1, Wl - 1);
    int y1 = min(y0 + 1, Hl - 1);
    int base = b * Hl * Wl * Dm;

    int4 off;
    off.x = base + (y0 * Wl + x0) * Dm;
    off.y = base + (y0 * Wl + x1) * Dm;
    off.z = base + (y1 * Wl + x0) * Dm;
    off.w = base + (y1 * Wl + x1) * Dm;
    g_soff[qidx * 16 + p] = off;

    float4 cw;
    cw.x = (1.f - wx) * (1.f - wy) * wattn;
    cw.y = wx * (1.f - wy) * wattn;
    cw.z = (1.f - wx) * wy * wattn;
    cw.w = wx * wy * wattn;
    g_cw[qidx * 16 + p] = cw;
}

// ---------------------------------------------------------------------------
// Kernel 4: gather, warp-per-query. 8 queries per block, 4096 blocks.
// Combined corner weights: acc[ch] += w00*v00 + w01*v01 + w10*v10 + w11*v11
// ---------------------------------------------------------------------------
__global__ __launch_bounds__(256) void gather_kernel()
{
    __shared__ int4   soff[8][16];
    __shared__ float4 scw [8][16];

    const int tid  = threadIdx.x;
    const int w    = tid >> 5;
    const int lane = tid & 31;
    const int q0   = blockIdx.x * 8;

    if (tid < 128) {
        int qq = tid >> 4, pp = tid & 15;
        soff[qq][pp] = g_soff[(q0 + qq) * 16 + pp];
        scw [qq][pp] = g_cw  [(q0 + qq) * 16 + pp];
    }
    __syncthreads();

    const int qidx = q0 + w;
    const int co   = lane * 8;
    float acc[8] = {};

#pragma unroll
    for (int p = 0; p < 16; p++) {
        const int4   o  = soff[w][p];
        const float4 cw = scw[w][p];
        const __half* mp = (p < 8) ? g_map0 : g_map1;

        float4 r00 = __ldg((const float4*)(mp + o.x + co));
        float4 r01 = __ldg((const float4*)(mp + o.y + co));
        float4 r10 = __ldg((const float4*)(mp + o.z + co));
        float4 r11 = __ldg((const float4*)(mp + o.w + co));
        const __half2* h00 = (const __half2*)&r00;
        const __half2* h01 = (const __half2*)&r01;
        const __half2* h10 = (const __half2*)&r10;
        const __half2* h11 = (const __half2*)&r11;

#pragma unroll
        for (int j = 0; j < 4; j++) {
            float2 f00 = __half22float2(h00[j]);
            float2 f01 = __half22float2(h01[j]);
            float2 f10 = __half22float2(h10[j]);
            float2 f11 = __half22float2(h11[j]);
            acc[2 * j + 0] += cw.x * f00.x + cw.y * f01.x + cw.z * f10.x + cw.w * f11.x;
            acc[2 * j + 1] += cw.x * f00.y + cw.y * f01.y + cw.z * f10.y + cw.w * f11.y;
        }
    }

    __half2 hv[4];
#pragma unroll
    for (int j = 0; j < 4; j++)
        hv[j] = __floats2half2_rn(acc[2 * j], acc[2 * j + 1]);
    *(uint4*)&g_pre16[(size_t)qidx * 256 + co] = *(uint4*)hv;
}

// ---------------------------------------------------------------------------
// Kernel 5: C = g_pre16(M,256) @ Wout16(256,256) + bout  via HMMA m16n8k16.
// 2-stage cp.async pipeline over k-chunks of 32.
// ---------------------------------------------------------------------------
#define HAPITCH 40
#define HBPITCH 136

__global__ __launch_bounds__(256) void gemm_hmma_kernel(
    const float* __restrict__ bias, float* __restrict__ C)
{
    __shared__ __align__(16) __half As[2][128 * HAPITCH];
    __shared__ __align__(16) __half Bs[2][32 * HBPITCH];

    const int tid  = threadIdx.x;
    const int wid  = tid >> 5;
    const int lane = tid & 31;
    const int m0 = blockIdx.y * 128;
    const int n0 = blockIdx.x * 128;
    const int wm = (wid & 1) * 64;
    const int wn = (wid >> 1) * 32;

    // cp.async source/dest indices
    const int ara = tid >> 2;            // A row 0..63 (iter adds 64)
    const int aca = (tid & 3) * 8;       // A col in halves (8 halves = 16B)
    const int brb = tid >> 4;            // B k-row 0..15 (iter adds 16)
    const int bcb = (tid & 15) * 8;      // B n-col in halves

    float acc[4][4][4] = {};

    const int lr = lane & 15;
    const int lc = (lane >> 4) * 8;

    // prologue
    {
        const int k0 = 0;
        cpa16(smem_u32(&As[0][ara * HAPITCH + aca]),
              &g_pre16[(size_t)(m0 + ara) * 256 + k0 + aca]);
        cpa16(smem_u32(&As[0][(ara + 64) * HAPITCH + aca]),
              &g_pre16[(size_t)(m0 + ara + 64) * 256 + k0 + aca]);
        cpa16(smem_u32(&Bs[0][brb * HBPITCH + bcb]),
              &g_Wout16[(size_t)(k0 + brb) * 256 + n0 + bcb]);
        cpa16(smem_u32(&Bs[0][(brb + 16) * HBPITCH + bcb]),
              &g_Wout16[(size_t)(k0 + brb + 16) * 256 + n0 + bcb]);
        asm volatile("cp.async.commit_group;");
    }

#pragma unroll
    for (int it = 0; it < 8; it++) {
        if (it + 1 < 8) {
            const int k0 = (it + 1) * 32;
            const int s = (it + 1) & 1;
            cpa16(smem_u32(&As[s][ara * HAPITCH + aca]),
                  &g_pre16[(size_t)(m0 + ara) * 256 + k0 + aca]);
            cpa16(smem_u32(&As[s][(ara + 64) * HAPITCH + aca]),
                  &g_pre16[(size_t)(m0 + ara + 64) * 256 + k0 + aca]);
            cpa16(smem_u32(&Bs[s][brb * HBPITCH + bcb]),
                  &g_Wout16[(size_t)(k0 + brb) * 256 + n0 + bcb]);
            cpa16(smem_u32(&Bs[s][(brb + 16) * HBPITCH + bcb]),
                  &g_Wout16[(size_t)(k0 + brb + 16) * 256 + n0 + bcb]);
            asm volatile("cp.async.commit_group;");
            asm volatile("cp.async.wait_group 1;");
        } else {
            asm volatile("cp.async.wait_group 0;");
        }
        __syncthreads();

        const int s = it & 1;
#pragma unroll
        for (int kk = 0; kk < 32; kk += 16) {
            unsigned a[4][4];
#pragma unroll
            for (int mt = 0; mt < 4; mt++) {
                unsigned addr = smem_u32(&As[s][(wm + mt * 16 + lr) * HAPITCH + kk + lc]);
                asm volatile(
                    "ldmatrix.sync.aligned.m8n8.x4.shared.b16 {%0,%1,%2,%3}, [%4];"
                    : "=r"(a[mt][0]), "=r"(a[mt][1]), "=r"(a[mt][2]), "=r"(a[mt][3])
                    : "r"(addr));
            }
            unsigned b[2][4];
#pragma unroll
            for (int ng = 0; ng < 2; ng++) {
                unsigned addr = smem_u32(&Bs[s][(kk + lr) * HBPITCH + wn + ng * 16 + lc]);
                asm volatile(
                    "ldmatrix.sync.aligned.m8n8.x4.trans.shared.b16 {%0,%1,%2,%3}, [%4];"
                    : "=r"(b[ng][0]), "=r"(b[ng][1]), "=r"(b[ng][2]), "=r"(b[ng][3])
                    : "r"(addr));
            }
#pragma unroll
            for (int mt = 0; mt < 4; mt++) {
#pragma unroll
                for (int nt = 0; nt < 4; nt++) {
                    unsigned b0 = b[nt >> 1][(nt & 1) * 2 + 0];
                    unsigned b1 = b[nt >> 1][(nt & 1) * 2 + 1];
                    asm volatile(
                        "mma.sync.aligned.m16n8k16.row.col.f32.f16.f16.f32 "
                        "{%0,%1,%2,%3}, {%4,%5,%6,%7}, {%8,%9}, {%0,%1,%2,%3};"
                        : "+f"(acc[mt][nt][0]), "+f"(acc[mt][nt][1]),
                          "+f"(acc[mt][nt][2]), "+f"(acc[mt][nt][3])
                        : "r"(a[mt][0]), "r"(a[mt][1]), "r"(a[mt][2]), "r"(a[mt][3]),
                          "r"(b0), "r"(b1));
                }
            }
        }
        __syncthreads();
    }

    const int gr = lane >> 2;
    const int gc = (lane & 3) * 2;
#pragma unroll
    for (int mt = 0; mt < 4; mt++) {
#pragma unroll
        for (int nt = 0; nt < 4; nt++) {
            int col = n0 + wn + nt * 8 + gc;
            float2 bv = *(const float2*)&bias[col];
            int row0 = m0 + wm + mt * 16 + gr;
            float2 o0 = make_float2(acc[mt][nt][0] + bv.x, acc[mt][nt][1] + bv.y);
            float2 o1 = make_float2(acc[mt][nt][2] + bv.x, acc[mt][nt][3] + bv.y);
            *(float2*)&C[(size_t)row0 * 256 + col]       = o0;
            *(float2*)&C[(size_t)(row0 + 8) * 256 + col] = o1;
        }
    }
}

// ---------------------------------------------------------------------------
extern "C" void kernel_launch(void* const* d_in, const int* in_sizes, int n_in,
                              void* d_out, int out_size)
{
    const float* q        = (const float*)d_in[0];
    const float* map0     = (const float*)d_in[1];
    const float* map1     = (const float*)d_in[2];
    const float* base_ref = (const float*)d_in[3];
    const float* Wrd      = (const float*)d_in[4];
    const float* brd      = (const float*)d_in[5];
    const float* Woff     = (const float*)d_in[6];
    const float* boff     = (const float*)d_in[7];
    const float* Wattn    = (const float*)d_in[8];
    const float* battn    = (const float*)d_in[9];
    const float* Wout     = (const float*)d_in[10];
    const float* bout     = (const float*)d_in[11];
    float* out = (float*)d_out;

    pack_weights_kernel<<<64, 256>>>(Wrd, brd, Woff, boff, Wattn, battn);
    pack_wout_kernel<<<128, 256>>>(Wout);

    transpose_kernel<<<dim3((H0 * W0) / 32, Dm / 64, Bn), 256>>>(map0, H0 * W0, 0);
    transpose_kernel<<<dim3((H1 * W1) / 32, Dm / 64, Bn), 256>>>(map1, H1 * W1, 1);

    proj_gemm_kernel<<<NQ / 64, 256>>>(q);

    coord_kernel<<<NQ / 16, 256>>>(base_ref);

    gather_kernel<<<NQ / 8, 256>>>();

    gemm_hmma_kernel<<<dim3(2, NQ / 128), 256>>>(bout, out);
}

// round 9
// speedup vs baseline: 10.2089x; 1.0140x over previous
#include <cuda_runtime.h>
#include <cuda_fp16.h>
#include <math.h>

#define Bn 4
#define Qn 8192
#define Dm 256
#define Lv 2
#define Pp 8
#define H0 128
#define W0 128
#define H1 64
#define W1 64
#define EPSV 1e-5f
#define NQ (Bn * Qn)          // 32768 total queries

// Scratch (device globals — no allocations allowed)
__device__ __half g_map0[Bn * H0 * W0 * Dm];   // (B, H*W, D) HWC fp16
__device__ __half g_map1[Bn * H1 * W1 * Dm];
__device__ __half g_pre16[NQ * Dm];            // pre-Wout accumulator (fp16)
__device__ __half g_Wout16[Dm * Dm];           // Wout in fp16
__device__ float  g_WcatKM[256 * 64];          // packed weights, k-major [k][j]
__device__ float  g_bcatP[64];
__device__ float  g_dots[NQ * 64];             // projection outputs per query

__device__ __forceinline__ unsigned smem_u32(const void* p) {
    return (unsigned)__cvta_generic_to_shared(p);
}
__device__ __forceinline__ void cpa16(unsigned d, const void* s) {
    asm volatile("cp.async.cg.shared.global [%0], [%1], 16;" :: "r"(d), "l"(s));
}

// ---------------------------------------------------------------------------
// Kernel 0a: pack projection weights k-major into g_WcatKM[k][j] (j 52..63 = 0)
// ---------------------------------------------------------------------------
__global__ __launch_bounds__(256) void pack_weights_kernel(
    const float* __restrict__ Wrd,  const float* __restrict__ brd,
    const float* __restrict__ Woff, const float* __restrict__ boff,
    const float* __restrict__ Wattn,const float* __restrict__ battn)
{
    int j = blockIdx.x;
    int k = threadIdx.x;
    float v = 0.f, bv = 0.f;
    if (j < 4)       { v = Wrd  [k * 4  + j];      bv = brd  [j]; }
    else if (j < 36) { v = Woff [k * 32 + (j-4)];  bv = boff [j-4]; }
    else if (j < 52) { v = Wattn[k * 16 + (j-36)]; bv = battn[j-36]; }
    g_WcatKM[k * 64 + j] = v;
    if (k == 0) g_bcatP[j] = bv;
}

// ---------------------------------------------------------------------------
// Kernel 0b: Wout fp32 -> fp16 (same (k,n) row-major layout)
// ---------------------------------------------------------------------------
__global__ __launch_bounds__(256) void pack_wout_kernel(const float* __restrict__ Wout)
{
    int idx = blockIdx.x * 256 + threadIdx.x;    // half2 index
    float2 v = ((const float2*)Wout)[idx];
    ((__half2*)g_Wout16)[idx] = __floats2half2_rn(v.x, v.y);
}

// ---------------------------------------------------------------------------
// Kernel 1: both maps (B, D, HW) -> (B, HW, D) tiled transpose, fp32 -> fp16.
// blockIdx.x < 512 -> map0 tiles, else map1 tiles. One launch.
// ---------------------------------------------------------------------------
__global__ __launch_bounds__(256) void transpose_both_kernel(
    const float* __restrict__ map0, const float* __restrict__ map1)
{
    __shared__ float tile[64][33];

    const int bx    = blockIdx.x;
    const int level = (bx >= 512);
    const int HW    = level ? (H1 * W1) : (H0 * W0);
    const int hw0   = (level ? (bx - 512) : bx) * 32;
    const float* in = level ? map1 : map0;
    __half* out     = level ? g_map1 : g_map0;

    const int d0  = blockIdx.y * 64;
    const int b   = blockIdx.z;
    const int tid  = threadIdx.x;
    const int tx   = tid & 31;
    const int ty   = tid >> 5;

    const float* inb = in + (size_t)b * Dm * HW;
    __half* outb = out + (size_t)b * HW * Dm;

#pragma unroll
    for (int i = 0; i < 8; i++) {
        int d = d0 + ty + 8 * i;
        tile[ty + 8 * i][tx] = inb[(size_t)d * HW + hw0 + tx];
    }
    __syncthreads();

#pragma unroll
    for (int i = 0; i < 4; i++) {
        int hw = ty + 8 * i;
        __half2 v = __floats2half2_rn(tile[2 * tx][hw], tile[2 * tx + 1][hw]);
        ((__half2*)(outb + (size_t)(hw0 + hw) * Dm + d0))[tx] = v;
    }
}

// ---------------------------------------------------------------------------
// Kernel 2: projection GEMM  g_dots[NQ][64] = q(NQ x 256) @ Wcat + bcat
// BM=64, BN=64, BK=32, 2-stage cp.async pipeline, 4x4 microtile.
// ---------------------------------------------------------------------------
#define APITCH 36    // 144B rows, 16B aligned
#define BKPITCH 68   // 272B rows, 16B aligned

__global__ __launch_bounds__(256) void proj_gemm_kernel(const float* __restrict__ q)
{
    __shared__ __align__(16) float As[2][64 * APITCH];   // [m][k] row-major
    __shared__ __align__(16) float Bs[2][32 * BKPITCH];  // [k][n] k-major

    const int tid = threadIdx.x;
    const int m0 = blockIdx.x * 64;
    const int tx = tid & 15;       // n: tx*4
    const int ty = tid >> 4;       // m: ty*4

    const int ar = tid >> 3;            // A row (0..63 over 2 iters)
    const int ac = (tid & 7) * 4;       // A col (float4)
    const int br = tid >> 4;            // B k-row (0..31 over 2 iters)
    const int bc = (tid & 15) * 4;      // B n-col (float4)

    // ---- prologue: stage 0 ----
    {
        const int k0 = 0;
        cpa16(smem_u32(&As[0][ar * APITCH + ac]),          &q[(size_t)(m0 + ar) * 256 + k0 + ac]);
        cpa16(smem_u32(&As[0][(ar + 32) * APITCH + ac]),   &q[(size_t)(m0 + ar + 32) * 256 + k0 + ac]);
        cpa16(smem_u32(&Bs[0][br * BKPITCH + bc]),         &g_WcatKM[(k0 + br) * 64 + bc]);
        cpa16(smem_u32(&Bs[0][(br + 16) * BKPITCH + bc]),  &g_WcatKM[(k0 + br + 16) * 64 + bc]);
        asm volatile("cp.async.commit_group;");
    }

    float acc[4][4] = {};

#pragma unroll
    for (int it = 0; it < 8; it++) {
        if (it + 1 < 8) {
            const int k0 = (it + 1) * 32;
            const int s = (it + 1) & 1;
            cpa16(smem_u32(&As[s][ar * APITCH + ac]),          &q[(size_t)(m0 + ar) * 256 + k0 + ac]);
            cpa16(smem_u32(&As[s][(ar + 32) * APITCH + ac]),   &q[(size_t)(m0 + ar + 32) * 256 + k0 + ac]);
            cpa16(smem_u32(&Bs[s][br * BKPITCH + bc]),         &g_WcatKM[(k0 + br) * 64 + bc]);
            cpa16(smem_u32(&Bs[s][(br + 16) * BKPITCH + bc]),  &g_WcatKM[(k0 + br + 16) * 64 + bc]);
            asm volatile("cp.async.commit_group;");
            asm volatile("cp.async.wait_group 1;");
        } else {
            asm volatile("cp.async.wait_group 0;");
        }
        __syncthreads();

        const int s = it & 1;
#pragma unroll
        for (int kk = 0; kk < 32; kk += 4) {
            float4 a[4], b[4];
#pragma unroll
            for (int i = 0; i < 4; i++)
                a[i] = *(const float4*)&As[s][(ty * 4 + i) * APITCH + kk];
#pragma unroll
            for (int j = 0; j < 4; j++)
                b[j] = *(const float4*)&Bs[s][(kk + j) * BKPITCH + tx * 4];
#pragma unroll
            for (int kj = 0; kj < 4; kj++) {
                float av[4];
#pragma unroll
                for (int i = 0; i < 4; i++)
                    av[i] = ((const float*)&a[i])[kj];
                const float* bv = (const float*)&b[kj];
#pragma unroll
                for (int i = 0; i < 4; i++)
#pragma unroll
                    for (int j = 0; j < 4; j++)
                        acc[i][j] += av[i] * bv[j];
            }
        }
        __syncthreads();
    }

    float4 bb = *(const float4*)&g_bcatP[tx * 4];
    float bv[4] = {bb.x, bb.y, bb.z, bb.w};
#pragma unroll
    for (int i = 0; i < 4; i++) {
        int m = m0 + ty * 4 + i;
        float4 o;
        o.x = acc[i][0] + bv[0];
        o.y = acc[i][1] + bv[1];
        o.z = acc[i][2] + bv[2];
        o.w = acc[i][3] + bv[3];
        *(float4*)&g_dots[(size_t)m * 64 + tx * 4] = o;
    }
}

// ---------------------------------------------------------------------------
// Kernel 3: FUSED coords + softmax + gather. 16 queries per block, 2048 blocks.
// Phase 1: 256 threads = 16 queries x 16 points -> smem offsets + weights.
// Phase 2: warp w gathers queries 2w and 2w+1 (lane owns 8 channels).
// ---------------------------------------------------------------------------
__global__ __launch_bounds__(256) void gather_fused_kernel(
    const float* __restrict__ base_ref)
{
    __shared__ int4   soff[16][16];
    __shared__ float4 scw [16][16];

    const int tid = threadIdx.x;
    const int q0  = blockIdx.x * 16;

    // ---------- Phase 1: coordinates + softmax ----------
    {
        const int qq = tid >> 4;          // query within block (0..15)
        const int p  = tid & 15;          // point (0..15)
        const int qidx = q0 + qq;
        const int b = qidx >> 13;         // Qn = 8192

        const float* dots = &g_dots[(size_t)qidx * 64];

        float logit = dots[36 + p];
        float m = logit;
#pragma unroll
        for (int o = 8; o; o >>= 1)
            m = fmaxf(m, __shfl_xor_sync(0xffffffffu, m, o));
        float e = expf(logit - m);
        float esum = e;
#pragma unroll
        for (int o = 8; o; o >>= 1)
            esum += __shfl_xor_sync(0xffffffffu, esum, o);
        float wattn = e / esum;

        const int l  = p >> 3;
        const int pp = p & 7;
        const int Wl = l ? W1 : W0;
        const int Hl = l ? H1 : H0;

        float bx = base_ref[(b * Lv + l) * 2 + 0];
        float by = base_ref[(b * Lv + l) * 2 + 1];
        bx = fminf(fmaxf(bx, EPSV), 1.f - EPSV);
        by = fminf(fmaxf(by, EPSV), 1.f - EPSV);
        float lbx = logf(bx / (1.f - bx));
        float lby = logf(by / (1.f - by));
        float rx = 1.f / (1.f + expf(-(lbx + dots[l * 2 + 0])));
        float ry = 1.f / (1.f + expf(-(lby + dots[l * 2 + 1])));

        float ox = dots[4 + l * 16 + pp * 2 + 0];
        float oy = dots[4 + l * 16 + pp * 2 + 1];
        float lx = rx + ox / (float)Wl;
        float ly = ry + oy / (float)Hl;
        if (l == 1) ly = ly - floorf(ly);   // jnp.remainder(ly, 1.0)

        float x = lx * (float)Wl - 0.5f;
        float y = ly * (float)Hl - 0.5f;
        x = fminf(fmaxf(x, 0.f), (float)(Wl - 1));
        y = fminf(fmaxf(y, 0.f), (float)(Hl - 1));
        float x0f = floorf(x), y0f = floorf(y);
        float wx = x - x0f, wy = y - y0f;
        int x0 = (int)x0f, y0 = (int)y0f;
        int x1 = min(x0 + 1, Wl - 1);
        int y1 = min(y0 + 1, Hl - 1);
        int base = b * Hl * Wl * Dm;

        int4 off;
        off.x = base + (y0 * Wl + x0) * Dm;
        off.y = base + (y0 * Wl + x1) * Dm;
        off.z = base + (y1 * Wl + x0) * Dm;
        off.w = base + (y1 * Wl + x1) * Dm;
        soff[qq][p] = off;

        float4 cw;
        cw.x = (1.f - wx) * (1.f - wy) * wattn;
        cw.y = wx * (1.f - wy) * wattn;
        cw.z = (1.f - wx) * wy * wattn;
        cw.w = wx * wy * wattn;
        scw[qq][p] = cw;
    }
    __syncthreads();

    // ---------- Phase 2: gather ----------
    const int w    = tid >> 5;
    const int lane = tid & 31;
    const int co   = lane * 8;

#pragma unroll
    for (int h = 0; h < 2; h++) {
        const int qq = 2 * w + h;
        float acc[8] = {};

#pragma unroll
        for (int p = 0; p < 16; p++) {
            const int4   o  = soff[qq][p];
            const float4 cw = scw[qq][p];
            const __half* mp = (p < 8) ? g_map0 : g_map1;

            float4 r00 = __ldg((const float4*)(mp + o.x + co));
            float4 r01 = __ldg((const float4*)(mp + o.y + co));
            float4 r10 = __ldg((const float4*)(mp + o.z + co));
            float4 r11 = __ldg((const float4*)(mp + o.w + co));
            const __half2* h00 = (const __half2*)&r00;
            const __half2* h01 = (const __half2*)&r01;
            const __half2* h10 = (const __half2*)&r10;
            const __half2* h11 = (const __half2*)&r11;

#pragma unroll
            for (int j = 0; j < 4; j++) {
                float2 f00 = __half22float2(h00[j]);
                float2 f01 = __half22float2(h01[j]);
                float2 f10 = __half22float2(h10[j]);
                float2 f11 = __half22float2(h11[j]);
                acc[2 * j + 0] += cw.x * f00.x + cw.y * f01.x + cw.z * f10.x + cw.w * f11.x;
                acc[2 * j + 1] += cw.x * f00.y + cw.y * f01.y + cw.z * f10.y + cw.w * f11.y;
            }
        }

        __half2 hv[4];
#pragma unroll
        for (int j = 0; j < 4; j++)
            hv[j] = __floats2half2_rn(acc[2 * j], acc[2 * j + 1]);
        *(uint4*)&g_pre16[(size_t)(q0 + qq) * 256 + co] = *(uint4*)hv;
    }
}

// ---------------------------------------------------------------------------
// Kernel 4: C = g_pre16(M,256) @ Wout16(256,256) + bout  via HMMA m16n8k16.
// 2-stage cp.async pipeline over k-chunks of 32.
// ---------------------------------------------------------------------------
#define HAPITCH 40
#define HBPITCH 136

__global__ __launch_bounds__(256) void gemm_hmma_kernel(
    const float* __restrict__ bias, float* __restrict__ C)
{
    __shared__ __align__(16) __half As[2][128 * HAPITCH];
    __shared__ __align__(16) __half Bs[2][32 * HBPITCH];

    const int tid  = threadIdx.x;
    const int wid  = tid >> 5;
    const int lane = tid & 31;
    const int m0 = blockIdx.y * 128;
    const int n0 = blockIdx.x * 128;
    const int wm = (wid & 1) * 64;
    const int wn = (wid >> 1) * 32;

    const int ara = tid >> 2;            // A row 0..63 (iter adds 64)
    const int aca = (tid & 3) * 8;       // A col in halves
    const int brb = tid >> 4;            // B k-row 0..15 (iter adds 16)
    const int bcb = (tid & 15) * 8;      // B n-col in halves

    float acc[4][4][4] = {};

    const int lr = lane & 15;
    const int lc = (lane >> 4) * 8;

    {
        const int k0 = 0;
        cpa16(smem_u32(&As[0][ara * HAPITCH + aca]),
              &g_pre16[(size_t)(m0 + ara) * 256 + k0 + aca]);
        cpa16(smem_u32(&As[0][(ara + 64) * HAPITCH + aca]),
              &g_pre16[(size_t)(m0 + ara + 64) * 256 + k0 + aca]);
        cpa16(smem_u32(&Bs[0][brb * HBPITCH + bcb]),
              &g_Wout16[(size_t)(k0 + brb) * 256 + n0 + bcb]);
        cpa16(smem_u32(&Bs[0][(brb + 16) * HBPITCH + bcb]),
              &g_Wout16[(size_t)(k0 + brb + 16) * 256 + n0 + bcb]);
        asm volatile("cp.async.commit_group;");
    }

#pragma unroll
    for (int it = 0; it < 8; it++) {
        if (it + 1 < 8) {
            const int k0 = (it + 1) * 32;
            const int s = (it + 1) & 1;
            cpa16(smem_u32(&As[s][ara * HAPITCH + aca]),
                  &g_pre16[(size_t)(m0 + ara) * 256 + k0 + aca]);
            cpa16(smem_u32(&As[s][(ara + 64) * HAPITCH + aca]),
                  &g_pre16[(size_t)(m0 + ara + 64) * 256 + k0 + aca]);
            cpa16(smem_u32(&Bs[s][brb * HBPITCH + bcb]),
                  &g_Wout16[(size_t)(k0 + brb) * 256 + n0 + bcb]);
            cpa16(smem_u32(&Bs[s][(brb + 16) * HBPITCH + bcb]),
                  &g_Wout16[(size_t)(k0 + brb + 16) * 256 + n0 + bcb]);
            asm volatile("cp.async.commit_group;");
            asm volatile("cp.async.wait_group 1;");
        } else {
            asm volatile("cp.async.wait_group 0;");
        }
        __syncthreads();

        const int s = it & 1;
#pragma unroll
        for (int kk = 0; kk < 32; kk += 16) {
            unsigned a[4][4];
#pragma unroll
            for (int mt = 0; mt < 4; mt++) {
                unsigned addr = smem_u32(&As[s][(wm + mt * 16 + lr) * HAPITCH + kk + lc]);
                asm volatile(
                    "ldmatrix.sync.aligned.m8n8.x4.shared.b16 {%0,%1,%2,%3}, [%4];"
                    : "=r"(a[mt][0]), "=r"(a[mt][1]), "=r"(a[mt][2]), "=r"(a[mt][3])
                    : "r"(addr));
            }
            unsigned b[2][4];
#pragma unroll
            for (int ng = 0; ng < 2; ng++) {
                unsigned addr = smem_u32(&Bs[s][(kk + lr) * HBPITCH + wn + ng * 16 + lc]);
                asm volatile(
                    "ldmatrix.sync.aligned.m8n8.x4.trans.shared.b16 {%0,%1,%2,%3}, [%4];"
                    : "=r"(b[ng][0]), "=r"(b[ng][1]), "=r"(b[ng][2]), "=r"(b[ng][3])
                    : "r"(addr));
            }
#pragma unroll
            for (int mt = 0; mt < 4; mt++) {
#pragma unroll
                for (int nt = 0; nt < 4; nt++) {
                    unsigned b0 = b[nt >> 1][(nt & 1) * 2 + 0];
                    unsigned b1 = b[nt >> 1][(nt & 1) * 2 + 1];
                    asm volatile(
                        "mma.sync.aligned.m16n8k16.row.col.f32.f16.f16.f32 "
                        "{%0,%1,%2,%3}, {%4,%5,%6,%7}, {%8,%9}, {%0,%1,%2,%3};"
                        : "+f"(acc[mt][nt][0]), "+f"(acc[mt][nt][1]),
                          "+f"(acc[mt][nt][2]), "+f"(acc[mt][nt][3])
                        : "r"(a[mt][0]), "r"(a[mt][1]), "r"(a[mt][2]), "r"(a[mt][3]),
                          "r"(b0), "r"(b1));
                }
            }
        }
        __syncthreads();
    }

    const int gr = lane >> 2;
    const int gc = (lane & 3) * 2;
#pragma unroll
    for (int mt = 0; mt < 4; mt++) {
#pragma unroll
        for (int nt = 0; nt < 4; nt++) {
            int col = n0 + wn + nt * 8 + gc;
            float2 bv = *(const float2*)&bias[col];
            int row0 = m0 + wm + mt * 16 + gr;
            float2 o0 = make_float2(acc[mt][nt][0] + bv.x, acc[mt][nt][1] + bv.y);
            float2 o1 = make_float2(acc[mt][nt][2] + bv.x, acc[mt][nt][3] + bv.y);
            *(float2*)&C[(size_t)row0 * 256 + col]       = o0;
            *(float2*)&C[(size_t)(row0 + 8) * 256 + col] = o1;
        }
    }
}

// ---------------------------------------------------------------------------
extern "C" void kernel_launch(void* const* d_in, const int* in_sizes, int n_in,
                              void* d_out, int out_size)
{
    const float* q        = (const float*)d_in[0];
    const float* map0     = (const float*)d_in[1];
    const float* map1     = (const float*)d_in[2];
    const float* base_ref = (const float*)d_in[3];
    const float* Wrd      = (const float*)d_in[4];
    const float* brd      = (const float*)d_in[5];
    const float* Woff     = (const float*)d_in[6];
    const float* boff     = (const float*)d_in[7];
    const float* Wattn    = (const float*)d_in[8];
    const float* battn    = (const float*)d_in[9];
    const float* Wout     = (const float*)d_in[10];
    const float* bout     = (const float*)d_in[11];
    float* out = (float*)d_out;

    pack_weights_kernel<<<64, 256>>>(Wrd, brd, Woff, boff, Wattn, battn);
    pack_wout_kernel<<<128, 256>>>(Wout);

    transpose_both_kernel<<<dim3(512 + 128, Dm / 64, Bn), 256>>>(map0, map1);

    proj_gemm_kernel<<<NQ / 64, 256>>>(q);

    gather_fused_kernel<<<NQ / 16, 256>>>(base_ref);

    gemm_hmma_kernel<<<dim3(2, NQ / 128), 256>>>(bout, out);
}

// round 10
// speedup vs baseline: 10.8252x; 1.0604x over previous
#include <cuda_runtime.h>
#include <cuda_fp16.h>
#include <math.h>

#define Bn 4
#define Qn 8192
#define Dm 256
#define Lv 2
#define Pp 8
#define H0 128
#define W0 128
#define H1 64
#define W1 64
#define EPSV 1e-5f
#define NQ (Bn * Qn)          // 32768 total queries

// Scratch (device globals — no allocations allowed)
__device__ __half g_map0[Bn * H0 * W0 * Dm];   // (B, H*W, D) HWC fp16
__device__ __half g_map1[Bn * H1 * W1 * Dm];
__device__ __half g_pre16[NQ * Dm];            // pre-Wout accumulator (fp16)
__device__ __half g_Wout16[Dm * Dm];           // Wout in fp16
__device__ __half g_Wcat16h[256 * 64];         // packed proj weights hi, k-major [k][j]
__device__ __half g_Wcat16l[256 * 64];         // packed proj weights lo (residual)
__device__ float  g_bcatP[64];
__device__ float  g_dots[NQ * 64];             // projection outputs per query

__device__ __forceinline__ unsigned smem_u32(const void* p) {
    return (unsigned)__cvta_generic_to_shared(p);
}
__device__ __forceinline__ void cpa16(unsigned d, const void* s) {
    asm volatile("cp.async.cg.shared.global [%0], [%1], 16;" :: "r"(d), "l"(s));
}

// ---------------------------------------------------------------------------
// Kernel 0a: pack projection weights k-major, split into fp16 hi + lo.
// j: 0..3 = Wrd cols, 4..35 = Woff cols, 36..51 = Wattn cols, 52..63 zero.
// ---------------------------------------------------------------------------
__global__ __launch_bounds__(256) void pack_weights_kernel(
    const float* __restrict__ Wrd,  const float* __restrict__ brd,
    const float* __restrict__ Woff, const float* __restrict__ boff,
    const float* __restrict__ Wattn,const float* __restrict__ battn)
{
    int j = blockIdx.x;
    int k = threadIdx.x;
    float v = 0.f, bv = 0.f;
    if (j < 4)       { v = Wrd  [k * 4  + j];      bv = brd  [j]; }
    else if (j < 36) { v = Woff [k * 32 + (j-4)];  bv = boff [j-4]; }
    else if (j < 52) { v = Wattn[k * 16 + (j-36)]; bv = battn[j-36]; }
    __half hi = __float2half_rn(v);
    __half lo = __float2half_rn(v - __half2float(hi));
    g_Wcat16h[k * 64 + j] = hi;
    g_Wcat16l[k * 64 + j] = lo;
    if (k == 0) g_bcatP[j] = bv;
}

// ---------------------------------------------------------------------------
// Kernel 0b: Wout fp32 -> fp16 (same (k,n) row-major layout)
// ---------------------------------------------------------------------------
__global__ __launch_bounds__(256) void pack_wout_kernel(const float* __restrict__ Wout)
{
    int idx = blockIdx.x * 256 + threadIdx.x;    // half2 index
    float2 v = ((const float2*)Wout)[idx];
    ((__half2*)g_Wout16)[idx] = __floats2half2_rn(v.x, v.y);
}

// ---------------------------------------------------------------------------
// Kernel 1: both maps (B, D, HW) -> (B, HW, D) tiled transpose, fp32 -> fp16.
// ---------------------------------------------------------------------------
__global__ __launch_bounds__(256) void transpose_both_kernel(
    const float* __restrict__ map0, const float* __restrict__ map1)
{
    __shared__ float tile[64][33];

    const int bx    = blockIdx.x;
    const int level = (bx >= 512);
    const int HW    = level ? (H1 * W1) : (H0 * W0);
    const int hw0   = (level ? (bx - 512) : bx) * 32;
    const float* in = level ? map1 : map0;
    __half* out     = level ? g_map1 : g_map0;

    const int d0  = blockIdx.y * 64;
    const int b   = blockIdx.z;
    const int tid  = threadIdx.x;
    const int tx   = tid & 31;
    const int ty   = tid >> 5;

    const float* inb = in + (size_t)b * Dm * HW;
    __half* outb = out + (size_t)b * HW * Dm;

#pragma unroll
    for (int i = 0; i < 8; i++) {
        int d = d0 + ty + 8 * i;
        tile[ty + 8 * i][tx] = inb[(size_t)d * HW + hw0 + tx];
    }
    __syncthreads();

#pragma unroll
    for (int i = 0; i < 4; i++) {
        int hw = ty + 8 * i;
        __half2 v = __floats2half2_rn(tile[2 * tx][hw], tile[2 * tx + 1][hw]);
        ((__half2*)(outb + (size_t)(hw0 + hw) * Dm + d0))[tx] = v;
    }
}

// ---------------------------------------------------------------------------
// Kernel 2: projection GEMM via split-fp16 HMMA (fp32-accurate).
// g_dots[NQ][64] = q @ Wcat + bcat,  q = qh+ql, W = Wh+Wl,
// dots = qh*Wh + qh*Wl + ql*Wh (ql*Wl ~ 2.5e-7, dropped).
// BM=64 (grid 512), BK=64, 8 warps = 4(m) x 2(n), warp tile 16m x 32n.
// ---------------------------------------------------------------------------
#define PPITCH 72     // halves; 144B row stride (conflict-free for ldmatrix)

__global__ __launch_bounds__(256) void proj_hmma_kernel(const float* __restrict__ q)
{
    __shared__ __align__(16) __half Ah[64 * PPITCH];
    __shared__ __align__(16) __half Al[64 * PPITCH];
    __shared__ __align__(16) __half Bh[64 * PPITCH];
    __shared__ __align__(16) __half Bl[64 * PPITCH];

    const int tid  = threadIdx.x;
    const int wid  = tid >> 5;
    const int lane = tid & 31;
    const int m0 = blockIdx.x * 64;
    const int wm = (wid & 3) * 16;       // warp m offset
    const int wn = (wid >> 2) * 32;      // warp n offset

    const int lr = lane & 15;
    const int lc = (lane >> 4) * 8;

    float acc[4][4] = {};                // [nt][frag]

    for (int it = 0; it < 4; it++) {
        const int k0 = it * 64;

        // B tiles via cp.async (weights are tiny & L2-resident)
        {
            int r  = tid >> 3;           // two rows per thread via +32
            int c8 = (tid & 7) * 8;
            cpa16(smem_u32(&Bh[r * PPITCH + c8]),        &g_Wcat16h[(k0 + r) * 64 + c8]);
            cpa16(smem_u32(&Bh[(r + 32) * PPITCH + c8]), &g_Wcat16h[(k0 + r + 32) * 64 + c8]);
            cpa16(smem_u32(&Bl[r * PPITCH + c8]),        &g_Wcat16l[(k0 + r) * 64 + c8]);
            cpa16(smem_u32(&Bl[(r + 32) * PPITCH + c8]), &g_Wcat16l[(k0 + r + 32) * 64 + c8]);
            asm volatile("cp.async.commit_group;");
        }

        // A tile: LDG fp32, split to hi/lo fp16, STS
#pragma unroll
        for (int i = 0; i < 4; i++) {
            int idx = tid + i * 256;
            int r  = idx >> 4;           // 0..63
            int c4 = idx & 15;           // float4 col
            float4 v = *(const float4*)&q[(size_t)(m0 + r) * 256 + k0 + c4 * 4];
            float f[4] = {v.x, v.y, v.z, v.w};
            __half hi[4], lo[4];
#pragma unroll
            for (int j = 0; j < 4; j++) {
                hi[j] = __float2half_rn(f[j]);
                lo[j] = __float2half_rn(f[j] - __half2float(hi[j]));
            }
            int off = r * PPITCH + c4 * 4;
            *(__half2*)&Ah[off]     = __halves2half2(hi[0], hi[1]);
            *(__half2*)&Ah[off + 2] = __halves2half2(hi[2], hi[3]);
            *(__half2*)&Al[off]     = __halves2half2(lo[0], lo[1]);
            *(__half2*)&Al[off + 2] = __halves2half2(lo[2], lo[3]);
        }

        asm volatile("cp.async.wait_group 0;");
        __syncthreads();

#pragma unroll
        for (int kc = 0; kc < 4; kc++) {
            const int kk = kc * 16;
            unsigned ah[4], al[4];
            {
                unsigned addr = smem_u32(&Ah[(wm + lr) * PPITCH + kk + lc]);
                asm volatile(
                    "ldmatrix.sync.aligned.m8n8.x4.shared.b16 {%0,%1,%2,%3}, [%4];"
                    : "=r"(ah[0]), "=r"(ah[1]), "=r"(ah[2]), "=r"(ah[3]) : "r"(addr));
                addr = smem_u32(&Al[(wm + lr) * PPITCH + kk + lc]);
                asm volatile(
                    "ldmatrix.sync.aligned.m8n8.x4.shared.b16 {%0,%1,%2,%3}, [%4];"
                    : "=r"(al[0]), "=r"(al[1]), "=r"(al[2]), "=r"(al[3]) : "r"(addr));
            }
            unsigned bh[2][4], bl[2][4];
#pragma unroll
            for (int ng = 0; ng < 2; ng++) {
                unsigned addr = smem_u32(&Bh[(kk + lr) * PPITCH + wn + ng * 16 + lc]);
                asm volatile(
                    "ldmatrix.sync.aligned.m8n8.x4.trans.shared.b16 {%0,%1,%2,%3}, [%4];"
                    : "=r"(bh[ng][0]), "=r"(bh[ng][1]), "=r"(bh[ng][2]), "=r"(bh[ng][3])
                    : "r"(addr));
                addr = smem_u32(&Bl[(kk + lr) * PPITCH + wn + ng * 16 + lc]);
                asm volatile(
                    "ldmatrix.sync.aligned.m8n8.x4.trans.shared.b16 {%0,%1,%2,%3}, [%4];"
                    : "=r"(bl[ng][0]), "=r"(bl[ng][1]), "=r"(bl[ng][2]), "=r"(bl[ng][3])
                    : "r"(addr));
            }
#pragma unroll
            for (int nt = 0; nt < 4; nt++) {
                unsigned bh0 = bh[nt >> 1][(nt & 1) * 2 + 0];
                unsigned bh1 = bh[nt >> 1][(nt & 1) * 2 + 1];
                unsigned bl0 = bl[nt >> 1][(nt & 1) * 2 + 0];
                unsigned bl1 = bl[nt >> 1][(nt & 1) * 2 + 1];
                asm volatile(
                    "mma.sync.aligned.m16n8k16.row.col.f32.f16.f16.f32 "
                    "{%0,%1,%2,%3}, {%4,%5,%6,%7}, {%8,%9}, {%0,%1,%2,%3};"
                    : "+f"(acc[nt][0]), "+f"(acc[nt][1]), "+f"(acc[nt][2]), "+f"(acc[nt][3])
                    : "r"(ah[0]), "r"(ah[1]), "r"(ah[2]), "r"(ah[3]), "r"(bh0), "r"(bh1));
                asm volatile(
                    "mma.sync.aligned.m16n8k16.row.col.f32.f16.f16.f32 "
                    "{%0,%1,%2,%3}, {%4,%5,%6,%7}, {%8,%9}, {%0,%1,%2,%3};"
                    : "+f"(acc[nt][0]), "+f"(acc[nt][1]), "+f"(acc[nt][2]), "+f"(acc[nt][3])
                    : "r"(ah[0]), "r"(ah[1]), "r"(ah[2]), "r"(ah[3]), "r"(bl0), "r"(bl1));
                asm volatile(
                    "mma.sync.aligned.m16n8k16.row.col.f32.f16.f16.f32 "
                    "{%0,%1,%2,%3}, {%4,%5,%6,%7}, {%8,%9}, {%0,%1,%2,%3};"
                    : "+f"(acc[nt][0]), "+f"(acc[nt][1]), "+f"(acc[nt][2]), "+f"(acc[nt][3])
                    : "r"(al[0]), "r"(al[1]), "r"(al[2]), "r"(al[3]), "r"(bh0), "r"(bh1));
            }
        }
        __syncthreads();
    }

    // epilogue: + bias -> g_dots (fp32)
    const int gr = lane >> 2;
    const int gc = (lane & 3) * 2;
#pragma unroll
    for (int nt = 0; nt < 4; nt++) {
        int col = wn + nt * 8 + gc;
        float2 bv = *(const float2*)&g_bcatP[col];
        int row0 = m0 + wm + gr;
        float2 o0 = make_float2(acc[nt][0] + bv.x, acc[nt][1] + bv.y);
        float2 o1 = make_float2(acc[nt][2] + bv.x, acc[nt][3] + bv.y);
        *(float2*)&g_dots[(size_t)row0 * 64 + col]       = o0;
        *(float2*)&g_dots[(size_t)(row0 + 8) * 64 + col] = o1;
    }
}

// ---------------------------------------------------------------------------
// Kernel 3: FUSED coords + softmax + gather. 16 queries per block, 2048 blocks.
// ---------------------------------------------------------------------------
__global__ __launch_bounds__(256) void gather_fused_kernel(
    const float* __restrict__ base_ref)
{
    __shared__ int4   soff[16][16];
    __shared__ float4 scw [16][16];

    const int tid = threadIdx.x;
    const int q0  = blockIdx.x * 16;

    // ---------- Phase 1: coordinates + softmax ----------
    {
        const int qq = tid >> 4;          // query within block (0..15)
        const int p  = tid & 15;          // point (0..15)
        const int qidx = q0 + qq;
        const int b = qidx >> 13;         // Qn = 8192

        const float* dots = &g_dots[(size_t)qidx * 64];

        float logit = dots[36 + p];
        float m = logit;
#pragma unroll
        for (int o = 8; o; o >>= 1)
            m = fmaxf(m, __shfl_xor_sync(0xffffffffu, m, o));
        float e = expf(logit - m);
        float esum = e;
#pragma unroll
        for (int o = 8; o; o >>= 1)
            esum += __shfl_xor_sync(0xffffffffu, esum, o);
        float wattn = e / esum;

        const int l  = p >> 3;
        const int pp = p & 7;
        const int Wl = l ? W1 : W0;
        const int Hl = l ? H1 : H0;

        float bx = base_ref[(b * Lv + l) * 2 + 0];
        float by = base_ref[(b * Lv + l) * 2 + 1];
        bx = fminf(fmaxf(bx, EPSV), 1.f - EPSV);
        by = fminf(fmaxf(by, EPSV), 1.f - EPSV);
        float lbx = logf(bx / (1.f - bx));
        float lby = logf(by / (1.f - by));
        float rx = 1.f / (1.f + expf(-(lbx + dots[l * 2 + 0])));
        float ry = 1.f / (1.f + expf(-(lby + dots[l * 2 + 1])));

        float ox = dots[4 + l * 16 + pp * 2 + 0];
        float oy = dots[4 + l * 16 + pp * 2 + 1];
        float lx = rx + ox / (float)Wl;
        float ly = ry + oy / (float)Hl;
        if (l == 1) ly = ly - floorf(ly);   // jnp.remainder(ly, 1.0)

        float x = lx * (float)Wl - 0.5f;
        float y = ly * (float)Hl - 0.5f;
        x = fminf(fmaxf(x, 0.f), (float)(Wl - 1));
        y = fminf(fmaxf(y, 0.f), (float)(Hl - 1));
        float x0f = floorf(x), y0f = floorf(y);
        float wx = x - x0f, wy = y - y0f;
        int x0 = (int)x0f, y0 = (int)y0f;
        int x1 = min(x0 + 1, Wl - 1);
        int y1 = min(y0 + 1, Hl - 1);
        int base = b * Hl * Wl * Dm;

        int4 off;
        off.x = base + (y0 * Wl + x0) * Dm;
        off.y = base + (y0 * Wl + x1) * Dm;
        off.z = base + (y1 * Wl + x0) * Dm;
        off.w = base + (y1 * Wl + x1) * Dm;
        soff[qq][p] = off;

        float4 cw;
        cw.x = (1.f - wx) * (1.f - wy) * wattn;
        cw.y = wx * (1.f - wy) * wattn;
        cw.z = (1.f - wx) * wy * wattn;
        cw.w = wx * wy * wattn;
        scw[qq][p] = cw;
    }
    __syncthreads();

    // ---------- Phase 2: gather ----------
    const int w    = tid >> 5;
    const int lane = tid & 31;
    const int co   = lane * 8;

#pragma unroll
    for (int h = 0; h < 2; h++) {
        const int qq = 2 * w + h;
        float acc[8] = {};

#pragma unroll
        for (int p = 0; p < 16; p++) {
            const int4   o  = soff[qq][p];
            const float4 cw = scw[qq][p];
            const __half* mp = (p < 8) ? g_map0 : g_map1;

            float4 r00 = __ldg((const float4*)(mp + o.x + co));
            float4 r01 = __ldg((const float4*)(mp + o.y + co));
            float4 r10 = __ldg((const float4*)(mp + o.z + co));
            float4 r11 = __ldg((const float4*)(mp + o.w + co));
            const __half2* h00 = (const __half2*)&r00;
            const __half2* h01 = (const __half2*)&r01;
            const __half2* h10 = (const __half2*)&r10;
            const __half2* h11 = (const __half2*)&r11;

#pragma unroll
            for (int j = 0; j < 4; j++) {
                float2 f00 = __half22float2(h00[j]);
                float2 f01 = __half22float2(h01[j]);
                float2 f10 = __half22float2(h10[j]);
                float2 f11 = __half22float2(h11[j]);
                acc[2 * j + 0] += cw.x * f00.x + cw.y * f01.x + cw.z * f10.x + cw.w * f11.x;
                acc[2 * j + 1] += cw.x * f00.y + cw.y * f01.y + cw.z * f10.y + cw.w * f11.y;
            }
        }

        __half2 hv[4];
#pragma unroll
        for (int j = 0; j < 4; j++)
            hv[j] = __floats2half2_rn(acc[2 * j], acc[2 * j + 1]);
        *(uint4*)&g_pre16[(size_t)(q0 + qq) * 256 + co] = *(uint4*)hv;
    }
}

// ---------------------------------------------------------------------------
// Kernel 4: C = g_pre16(M,256) @ Wout16(256,256) + bout  via HMMA m16n8k16.
// ---------------------------------------------------------------------------
#define HAPITCH 40
#define HBPITCH 136

__global__ __launch_bounds__(256) void gemm_hmma_kernel(
    const float* __restrict__ bias, float* __restrict__ C)
{
    __shared__ __align__(16) __half As[2][128 * HAPITCH];
    __shared__ __align__(16) __half Bs[2][32 * HBPITCH];

    const int tid  = threadIdx.x;
    const int wid  = tid >> 5;
    const int lane = tid & 31;
    const int m0 = blockIdx.y * 128;
    const int n0 = blockIdx.x * 128;
    const int wm = (wid & 1) * 64;
    const int wn = (wid >> 1) * 32;

    const int ara = tid >> 2;
    const int aca = (tid & 3) * 8;
    const int brb = tid >> 4;
    const int bcb = (tid & 15) * 8;

    float acc[4][4][4] = {};

    const int lr = lane & 15;
    const int lc = (lane >> 4) * 8;

    {
        const int k0 = 0;
        cpa16(smem_u32(&As[0][ara * HAPITCH + aca]),
              &g_pre16[(size_t)(m0 + ara) * 256 + k0 + aca]);
        cpa16(smem_u32(&As[0][(ara + 64) * HAPITCH + aca]),
              &g_pre16[(size_t)(m0 + ara + 64) * 256 + k0 + aca]);
        cpa16(smem_u32(&Bs[0][brb * HBPITCH + bcb]),
              &g_Wout16[(size_t)(k0 + brb) * 256 + n0 + bcb]);
        cpa16(smem_u32(&Bs[0][(brb + 16) * HBPITCH + bcb]),
              &g_Wout16[(size_t)(k0 + brb + 16) * 256 + n0 + bcb]);
        asm volatile("cp.async.commit_group;");
    }

#pragma unroll
    for (int it = 0; it < 8; it++) {
        if (it + 1 < 8) {
            const int k0 = (it + 1) * 32;
            const int s = (it + 1) & 1;
            cpa16(smem_u32(&As[s][ara * HAPITCH + aca]),
                  &g_pre16[(size_t)(m0 + ara) * 256 + k0 + aca]);
            cpa16(smem_u32(&As[s][(ara + 64) * HAPITCH + aca]),
                  &g_pre16[(size_t)(m0 + ara + 64) * 256 + k0 + aca]);
            cpa16(smem_u32(&Bs[s][brb * HBPITCH + bcb]),
                  &g_Wout16[(size_t)(k0 + brb) * 256 + n0 + bcb]);
            cpa16(smem_u32(&Bs[s][(brb + 16) * HBPITCH + bcb]),
                  &g_Wout16[(size_t)(k0 + brb + 16) * 256 + n0 + bcb]);
            asm volatile("cp.async.commit_group;");
            asm volatile("cp.async.wait_group 1;");
        } else {
            asm volatile("cp.async.wait_group 0;");
        }
        __syncthreads();

        const int s = it & 1;
#pragma unroll
        for (int kk = 0; kk < 32; kk += 16) {
            unsigned a[4][4];
#pragma unroll
            for (int mt = 0; mt < 4; mt++) {
                unsigned addr = smem_u32(&As[s][(wm + mt * 16 + lr) * HAPITCH + kk + lc]);
                asm volatile(
                    "ldmatrix.sync.aligned.m8n8.x4.shared.b16 {%0,%1,%2,%3}, [%4];"
                    : "=r"(a[mt][0]), "=r"(a[mt][1]), "=r"(a[mt][2]), "=r"(a[mt][3])
                    : "r"(addr));
            }
            unsigned b[2][4];
#pragma unroll
            for (int ng = 0; ng < 2; ng++) {
                unsigned addr = smem_u32(&Bs[s][(kk + lr) * HBPITCH + wn + ng * 16 + lc]);
                asm volatile(
                    "ldmatrix.sync.aligned.m8n8.x4.trans.shared.b16 {%0,%1,%2,%3}, [%4];"
                    : "=r"(b[ng][0]), "=r"(b[ng][1]), "=r"(b[ng][2]), "=r"(b[ng][3])
                    : "r"(addr));
            }
#pragma unroll
            for (int mt = 0; mt < 4; mt++) {
#pragma unroll
                for (int nt = 0; nt < 4; nt++) {
                    unsigned b0 = b[nt >> 1][(nt & 1) * 2 + 0];
                    unsigned b1 = b[nt >> 1][(nt & 1) * 2 + 1];
                    asm volatile(
                        "mma.sync.aligned.m16n8k16.row.col.f32.f16.f16.f32 "
                        "{%0,%1,%2,%3}, {%4,%5,%6,%7}, {%8,%9}, {%0,%1,%2,%3};"
                        : "+f"(acc[mt][nt][0]), "+f"(acc[mt][nt][1]),
                          "+f"(acc[mt][nt][2]), "+f"(acc[mt][nt][3])
                        : "r"(a[mt][0]), "r"(a[mt][1]), "r"(a[mt][2]), "r"(a[mt][3]),
                          "r"(b0), "r"(b1));
                }
            }
        }
        __syncthreads();
    }

    const int gr = lane >> 2;
    const int gc = (lane & 3) * 2;
#pragma unroll
    for (int mt = 0; mt < 4; mt++) {
#pragma unroll
        for (int nt = 0; nt < 4; nt++) {
            int col = n0 + wn + nt * 8 + gc;
            float2 bv = *(const float2*)&bias[col];
            int row0 = m0 + wm + mt * 16 + gr;
            float2 o0 = make_float2(acc[mt][nt][0] + bv.x, acc[mt][nt][1] + bv.y);
            float2 o1 = make_float2(acc[mt][nt][2] + bv.x, acc[mt][nt][3] + bv.y);
            *(float2*)&C[(size_t)row0 * 256 + col]       = o0;
            *(float2*)&C[(size_t)(row0 + 8) * 256 + col] = o1;
        }
    }
}

// ---------------------------------------------------------------------------
extern "C" void kernel_launch(void* const* d_in, const int* in_sizes, int n_in,
                              void* d_out, int out_size)
{
    const float* q        = (const float*)d_in[0];
    const float* map0     = (const float*)d_in[1];
    const float* map1     = (const float*)d_in[2];
    const float* base_ref = (const float*)d_in[3];
    const float* Wrd      = (const float*)d_in[4];
    const float* brd      = (const float*)d_in[5];
    const float* Woff     = (const float*)d_in[6];
    const float* boff     = (const float*)d_in[7];
    const float* Wattn    = (const float*)d_in[8];
    const float* battn    = (const float*)d_in[9];
    const float* Wout     = (const float*)d_in[10];
    const float* bout     = (const float*)d_in[11];
    float* out = (float*)d_out;

    pack_weights_kernel<<<64, 256>>>(Wrd, brd, Woff, boff, Wattn, battn);
    pack_wout_kernel<<<128, 256>>>(Wout);

    transpose_both_kernel<<<dim3(512 + 128, Dm / 64, Bn), 256>>>(map0, map1);

    proj_hmma_kernel<<<NQ / 64, 256>>>(q);

    gather_fused_kernel<<<NQ / 16, 256>>>(base_ref);

    gemm_hmma_kernel<<<dim3(2, NQ / 128), 256>>>(bout, out);
}